// round 11
// baseline (speedup 1.0000x reference)
#include <cuda_runtime.h>
#include <cuda_bf16.h>
#include <math.h>
#include <stdint.h>

#define B_    256
#define C_    3
#define IMG_  32
#define D_    256
#define H_    8
#define HD_   32
#define T1_   65
#define MLPH_ 2048
#define HEADH_ 8192
#define NCLS_ 10
#define PDIM_ 48
#define ND_   (T1_*D_)   // 16640
#define SPLITK 4
#define KCHUNK (ND_/SPLITK)   // 4160

typedef __nv_bfloat16 bf16;
typedef __nv_bfloat162 bf162;

// ---------------- scratch ----------------------------------------------------
__device__ float g_out[B_*T1_*D_];
__device__ float g_qkv[B_*T1_*3*D_];
__device__ float g_hid[B_*HEADH_];
__device__ float g_part[SPLITK*B_*HEADH_];
__device__ bf16  g_hh[ND_*B_];          // A planes (h / p_out views)
__device__ bf16  g_hl[ND_*B_];
__device__ bf16  g_mh[(long)B_*T1_*MLPH_];
__device__ bf16  g_ml[(long)B_*T1_*MLPH_];
__device__ bf16  g_wqh[2*768*D_],  g_wql[2*768*D_];    // transposed [n][k]
__device__ bf16  g_w1h[2*MLPH_*D_], g_w1l[2*MLPH_*D_];
__device__ bf16  g_w2h[2*D_*MLPH_], g_w2l[2*D_*MLPH_];

// ---------------- helpers -----------------------------------------------------
__device__ __forceinline__ void split1(float v, bf16& h, bf16& l) {
    h = __float2bfloat16_rn(v);
    l = __float2bfloat16_rn(v - __bfloat162float(h));
}
__device__ __forceinline__ uint32_t smem_u32(const void* p) {
    uint32_t a;
    asm("{ .reg .u64 t; cvta.to.shared.u64 t, %1; cvt.u32.u64 %0, t; }" : "=r"(a) : "l"(p));
    return a;
}
__device__ __forceinline__ void ldsm_x4(uint32_t* r, uint32_t addr) {
    asm volatile("ldmatrix.sync.aligned.m8n8.x4.shared.b16 {%0,%1,%2,%3}, [%4];"
        : "=r"(r[0]), "=r"(r[1]), "=r"(r[2]), "=r"(r[3]) : "r"(addr));
}
__device__ __forceinline__ void mma16816(float* c, const uint32_t* a, const uint32_t* b) {
    asm volatile(
        "mma.sync.aligned.m16n8k16.row.col.f32.bf16.bf16.f32 "
        "{%0,%1,%2,%3}, {%4,%5,%6,%7}, {%8,%9}, {%0,%1,%2,%3};"
        : "+f"(c[0]), "+f"(c[1]), "+f"(c[2]), "+f"(c[3])
        : "r"(a[0]), "r"(a[1]), "r"(a[2]), "r"(a[3]), "r"(b[0]), "r"(b[1]));
}
__device__ __forceinline__ void split_pair(float x, float y, bf162& hi, bf162& lo) {
    hi = __float22bfloat162_rn(make_float2(x, y));
    float2 hf = __bfloat1622float2(hi);
    lo = __float22bfloat162_rn(make_float2(x - hf.x, y - hf.y));
}

// ---------------- patch embed + cls + positional encoding --------------------
__global__ void patch_embed_kernel(const float* __restrict__ x,
                                   const float* __restrict__ cls,
                                   const float* __restrict__ Wp,
                                   const float* __restrict__ bp,
                                   float* __restrict__ out) {
    int b = blockIdx.x;
    int t = blockIdx.y;
    int d = threadIdx.x;
    int i = d >> 1;
    float div = expf(-(float)(2 * i) * (9.210340371976184f / 256.0f));
    float ang = (float)t * div;
    float pe = (d & 1) ? cosf(ang) : sinf(ang);

    if (t == 0) {
        out[(b * T1_) * D_ + d] = cls[d] + pe;
    } else {
        __shared__ float sp[PDIM_];
        int tt = t - 1;
        int ni = tt >> 3, nj = tt & 7;
        if (d < PDIM_) {
            int c  = d / 16;
            int pi = (d >> 2) & 3;
            int pj = d & 3;
            sp[d] = x[((b * C_ + c) * IMG_ + ni * 4 + pi) * IMG_ + nj * 4 + pj];
        }
        __syncthreads();
        float acc = bp[d];
        #pragma unroll
        for (int k = 0; k < PDIM_; k++) acc += sp[k] * Wp[k * D_ + d];
        out[((b * T1_) + t) * D_ + d] = acc + pe;
    }
}

// ---------------- LayerNorm -> bf16 hi/lo planes ------------------------------
__global__ void ln2d_split_kernel(const float* __restrict__ X,
                                  const float* __restrict__ w,
                                  const float* __restrict__ bb,
                                  bf16* __restrict__ Yh, bf16* __restrict__ Yl) {
    int b = blockIdx.x;
    const float* xb = X + b * ND_;
    float s = 0.f, s2 = 0.f;
    for (int i = threadIdx.x; i < ND_; i += 256) {
        float v = xb[i];
        s += v; s2 += v * v;
    }
    __shared__ float rs[8], rs2[8], bc[2];
    #pragma unroll
    for (int o = 16; o > 0; o >>= 1) {
        s  += __shfl_down_sync(0xffffffffu, s,  o);
        s2 += __shfl_down_sync(0xffffffffu, s2, o);
    }
    int wid = threadIdx.x >> 5, lid = threadIdx.x & 31;
    if (lid == 0) { rs[wid] = s; rs2[wid] = s2; }
    __syncthreads();
    if (threadIdx.x == 0) {
        float ts = 0.f, ts2 = 0.f;
        #pragma unroll
        for (int k = 0; k < 8; k++) { ts += rs[k]; ts2 += rs2[k]; }
        float mu  = ts / (float)ND_;
        float var = ts2 / (float)ND_ - mu * mu;
        bc[0] = mu;
        bc[1] = rsqrtf(var + 1e-5f);
    }
    __syncthreads();
    float mu = bc[0], rsg = bc[1];
    bf16* yh = Yh + (long)b * ND_;
    bf16* yl = Yl + (long)b * ND_;
    for (int i = threadIdx.x; i < ND_; i += 256) {
        float v = (xb[i] - mu) * rsg * w[i] + bb[i];
        bf16 h, l; split1(v, h, l);
        yh[i] = h; yl[i] = l;
    }
}

// ---------------- fp32 -> bf16 hi/lo planes (elementwise) ---------------------
__global__ void split_plane_kernel(const float* __restrict__ X,
                                   bf16* __restrict__ Yh, bf16* __restrict__ Yl,
                                   long n) {
    long i = (long)blockIdx.x * 256 + threadIdx.x;
    if (i * 4 >= n) return;
    float4 v = *(const float4*)&X[i * 4];
    bf162 h0, l0, h1, l1;
    split_pair(v.x, v.y, h0, l0);
    split_pair(v.z, v.w, h1, l1);
    *(bf162*)&Yh[i * 4]     = h0;
    *(bf162*)&Yh[i * 4 + 2] = h1;
    *(bf162*)&Yl[i * 4]     = l0;
    *(bf162*)&Yl[i * 4 + 2] = l1;
}

// ---------------- W (K,N) fp32 -> transposed bf16 planes (N,K) ----------------
__global__ void convert_wt_kernel(const float* __restrict__ W,
                                  bf16* __restrict__ Th, bf16* __restrict__ Tl,
                                  int K, int N) {
    int idx = blockIdx.x * 256 + threadIdx.x;     // one per (n, k8)
    int k8s = K >> 3;
    if (idx >= N * k8s) return;
    int n = idx / k8s, k0 = (idx % k8s) * 8;
    bf16 hb[8], lb[8];
    #pragma unroll
    for (int j = 0; j < 8; j++) {
        float v = W[(long)(k0 + j) * N + n];
        split1(v, hb[j], lb[j]);
    }
    *(uint4*)&Th[(long)n * K + k0] = *(uint4*)hb;
    *(uint4*)&Tl[(long)n * K + k0] = *(uint4*)lb;
}

// ---------------- GEMM smem layout --------------------------------------------
#define PITCH 40
#define PITCHB (PITCH*2)
#define SA_H 0
#define SA_L 20480
#define SB_H 40960
#define SB_L 51200
#define BUFSZ 61440
#define GSMEM_TOTAL (2*BUFSZ)

// ---------------- fast GEMM: preconverted A planes + transposed W planes ------
// ACT: 0 none, 1 relu. RES adds R. OSPLIT writes bf16 hi/lo planes instead.
template<int ACT, bool RES, bool OSPLIT>
__global__ void __launch_bounds__(512, 1) gemm_fast(
    const bf16* __restrict__ Ah, const bf16* __restrict__ Al,
    const bf16* __restrict__ Bh, const bf16* __restrict__ Bl,
    const float* __restrict__ bias, const float* __restrict__ R,
    float* __restrict__ Cc, bf16* __restrict__ Oh, bf16* __restrict__ Ol,
    int M, int N, int K)
{
    extern __shared__ char smem[];
    const int tid = threadIdx.x;
    const int wid = tid >> 5;
    const int lane = tid & 31;
    const int wm = wid >> 2, wn = wid & 3;
    const int m0 = blockIdx.y * 256, n0 = blockIdx.x * 128;
    const int gid = lane >> 2, tig = lane & 3;

    const uint32_t smem_u = smem_u32(smem);
    const int arow_l = wm * 64 + (lane & 15);
    const int kadd_a = (lane & 16) ? 16 : 0;
    const int brow_l = wn * 32 + (lane & 7) + ((lane & 16) ? 8 : 0);
    const int kadd_b = (lane & 8) ? 16 : 0;

    float c[4][4][4];
    #pragma unroll
    for (int i = 0; i < 4; i++)
        #pragma unroll
        for (int j = 0; j < 4; j++)
            #pragma unroll
            for (int r = 0; r < 4; r++) c[i][j][r] = 0.f;

    const int nk = K / 32;
    uint4 rah[2], ral[2], rbh, rbl;

    // A: 256x32 per plane = 1024 uint4, 2/thread; B: 128x32 = 512 uint4, 1/thread
    const int ar0 = tid >> 2, aq = tid & 3;          // +512: row+128
    const int br = tid >> 2, bq = tid & 3;

    auto ldg_tile = [&](int t) {
        const long ka = (long)t * 32 + aq * 8;
        rah[0] = *(const uint4*)&Ah[(long)(m0 + ar0) * K + ka];
        rah[1] = *(const uint4*)&Ah[(long)(m0 + ar0 + 128) * K + ka];
        ral[0] = *(const uint4*)&Al[(long)(m0 + ar0) * K + ka];
        ral[1] = *(const uint4*)&Al[(long)(m0 + ar0 + 128) * K + ka];
        const long kb = (long)t * 32 + bq * 8;
        rbh = *(const uint4*)&Bh[(long)(n0 + br) * K + kb];
        rbl = *(const uint4*)&Bl[(long)(n0 + br) * K + kb];
    };
    auto sts_tile = [&](int buf) {
        char* base = smem + buf * BUFSZ;
        *(uint4*)(base + SA_H + (ar0 * PITCH + aq * 8) * 2)          = rah[0];
        *(uint4*)(base + SA_H + ((ar0 + 128) * PITCH + aq * 8) * 2)  = rah[1];
        *(uint4*)(base + SA_L + (ar0 * PITCH + aq * 8) * 2)          = ral[0];
        *(uint4*)(base + SA_L + ((ar0 + 128) * PITCH + aq * 8) * 2)  = ral[1];
        *(uint4*)(base + SB_H + (br * PITCH + bq * 8) * 2)           = rbh;
        *(uint4*)(base + SB_L + (br * PITCH + bq * 8) * 2)           = rbl;
    };

    ldg_tile(0);
    sts_tile(0);
    __syncthreads();

    for (int t = 0; t < nk; t++) {
        const int buf = t & 1;
        if (t + 1 < nk) ldg_tile(t + 1);
        const uint32_t bufb = smem_u + buf * BUFSZ;

        #pragma unroll
        for (int ks = 0; ks < 2; ks++) {
            const int kb = ks * 32;
            uint32_t bh[4][2], bl[4][2];
            #pragma unroll
            for (int j = 0; j < 2; j++) {
                const uint32_t ab = bufb + (brow_l + j * 16) * PITCHB + kb + kadd_b;
                uint32_t r4[4];
                ldsm_x4(r4, ab + SB_H);
                bh[2*j][0] = r4[0]; bh[2*j][1] = r4[1];
                bh[2*j+1][0] = r4[2]; bh[2*j+1][1] = r4[3];
                ldsm_x4(r4, ab + SB_L);
                bl[2*j][0] = r4[0]; bl[2*j][1] = r4[1];
                bl[2*j+1][0] = r4[2]; bl[2*j+1][1] = r4[3];
            }
            #pragma unroll
            for (int am = 0; am < 4; am++) {
                const uint32_t aa = bufb + (arow_l + am * 16) * PITCHB + kb + kadd_a;
                uint32_t ah[4], al[4];
                ldsm_x4(ah, aa + SA_H);
                ldsm_x4(al, aa + SA_L);
                #pragma unroll
                for (int an = 0; an < 4; an++) {
                    mma16816(c[am][an], ah, bh[an]);
                    mma16816(c[am][an], ah, bl[an]);
                    mma16816(c[am][an], al, bh[an]);
                }
            }
        }

        if (t + 1 < nk) sts_tile(buf ^ 1);
        __syncthreads();
    }

    #pragma unroll
    for (int am = 0; am < 4; am++) {
        #pragma unroll
        for (int an = 0; an < 4; an++) {
            const int col = n0 + wn * 32 + an * 8 + tig * 2;
            const float bx = bias[col], by = bias[col + 1];
            #pragma unroll
            for (int hrow = 0; hrow < 2; hrow++) {
                const int m = m0 + wm * 64 + am * 16 + gid + hrow * 8;
                float vx = c[am][an][hrow * 2 + 0] + bx;
                float vy = c[am][an][hrow * 2 + 1] + by;
                if (ACT == 1) { vx = fmaxf(vx, 0.f); vy = fmaxf(vy, 0.f); }
                if (RES) {
                    const float2 r2 = *(const float2*)&R[(long)m * N + col];
                    vx += r2.x; vy += r2.y;
                }
                if (OSPLIT) {
                    bf162 hi, lo;
                    split_pair(vx, vy, hi, lo);
                    *(bf162*)&Oh[(long)m * N + col] = hi;
                    *(bf162*)&Ol[(long)m * N + col] = lo;
                } else {
                    *(float2*)&Cc[(long)m * N + col] = make_float2(vx, vy);
                }
            }
        }
    }
}

// ---------------- head1 GEMM: A planes + inline W split, split-K partials -----
__global__ void __launch_bounds__(512, 1) gemm_h1(
    const bf16* __restrict__ Ah, const bf16* __restrict__ Al,
    const float* __restrict__ W, float* __restrict__ Cc,
    int M, int N, int K, int kChunk)
{
    extern __shared__ char smem[];
    const int tid = threadIdx.x;
    const int wid = tid >> 5;
    const int lane = tid & 31;
    const int wm = wid >> 2, wn = wid & 3;
    const int m0 = blockIdx.y * 256, n0 = blockIdx.x * 128;
    const int kbase = blockIdx.z * kChunk;
    float* Cz = Cc + (long)blockIdx.z * M * N;
    const int gid = lane >> 2, tig = lane & 3;

    const uint32_t smem_u = smem_u32(smem);
    const int arow_l = wm * 64 + (lane & 15);
    const int kadd_a = (lane & 16) ? 16 : 0;
    const int brow_l = wn * 32 + (lane & 7) + ((lane & 16) ? 8 : 0);
    const int kadd_b = (lane & 8) ? 16 : 0;

    const int bn = tid & 127;
    const int bkh = (tid >> 7) * 8;
    const int ar0 = tid >> 2, aq = tid & 3;

    float c[4][4][4];
    #pragma unroll
    for (int i = 0; i < 4; i++)
        #pragma unroll
        for (int j = 0; j < 4; j++)
            #pragma unroll
            for (int r = 0; r < 4; r++) c[i][j][r] = 0.f;

    const int nk = kChunk / 32;
    uint4 rah[2], ral[2];
    float rb[8];

    auto ldg_tile = [&](int t) {
        const long ka = (long)kbase + t * 32 + aq * 8;
        rah[0] = *(const uint4*)&Ah[(long)(m0 + ar0) * K + ka];
        rah[1] = *(const uint4*)&Ah[(long)(m0 + ar0 + 128) * K + ka];
        ral[0] = *(const uint4*)&Al[(long)(m0 + ar0) * K + ka];
        ral[1] = *(const uint4*)&Al[(long)(m0 + ar0 + 128) * K + ka];
        const float* Wb = W + (long)(kbase + t * 32 + bkh) * N + n0 + bn;
        #pragma unroll
        for (int p = 0; p < 8; p++) rb[p] = Wb[(long)p * N];
    };
    auto sts_tile = [&](int buf) {
        char* base = smem + buf * BUFSZ;
        *(uint4*)(base + SA_H + (ar0 * PITCH + aq * 8) * 2)          = rah[0];
        *(uint4*)(base + SA_H + ((ar0 + 128) * PITCH + aq * 8) * 2)  = rah[1];
        *(uint4*)(base + SA_L + (ar0 * PITCH + aq * 8) * 2)          = ral[0];
        *(uint4*)(base + SA_L + ((ar0 + 128) * PITCH + aq * 8) * 2)  = ral[1];
        #pragma unroll
        for (int p = 0; p < 4; p++) {
            bf162 h, l;
            split_pair(rb[2 * p], rb[2 * p + 1], h, l);
            int e = bn * PITCH + bkh + 2 * p;
            *(bf162*)(base + SB_H + e * 2) = h;
            *(bf162*)(base + SB_L + e * 2) = l;
        }
    };

    ldg_tile(0);
    sts_tile(0);
    __syncthreads();

    for (int t = 0; t < nk; t++) {
        const int buf = t & 1;
        if (t + 1 < nk) ldg_tile(t + 1);
        const uint32_t bufb = smem_u + buf * BUFSZ;

        #pragma unroll
        for (int ks = 0; ks < 2; ks++) {
            const int kb = ks * 32;
            uint32_t bh[4][2], bl[4][2];
            #pragma unroll
            for (int j = 0; j < 2; j++) {
                const uint32_t ab = bufb + (brow_l + j * 16) * PITCHB + kb + kadd_b;
                uint32_t r4[4];
                ldsm_x4(r4, ab + SB_H);
                bh[2*j][0] = r4[0]; bh[2*j][1] = r4[1];
                bh[2*j+1][0] = r4[2]; bh[2*j+1][1] = r4[3];
                ldsm_x4(r4, ab + SB_L);
                bl[2*j][0] = r4[0]; bl[2*j][1] = r4[1];
                bl[2*j+1][0] = r4[2]; bl[2*j+1][1] = r4[3];
            }
            #pragma unroll
            for (int am = 0; am < 4; am++) {
                const uint32_t aa = bufb + (arow_l + am * 16) * PITCHB + kb + kadd_a;
                uint32_t ah[4], al[4];
                ldsm_x4(ah, aa + SA_H);
                ldsm_x4(al, aa + SA_L);
                #pragma unroll
                for (int an = 0; an < 4; an++) {
                    mma16816(c[am][an], ah, bh[an]);
                    mma16816(c[am][an], ah, bl[an]);
                    mma16816(c[am][an], al, bh[an]);
                }
            }
        }

        if (t + 1 < nk) sts_tile(buf ^ 1);
        __syncthreads();
    }

    #pragma unroll
    for (int am = 0; am < 4; am++)
        #pragma unroll
        for (int an = 0; an < 4; an++) {
            const int col = n0 + wn * 32 + an * 8 + tig * 2;
            #pragma unroll
            for (int hrow = 0; hrow < 2; hrow++) {
                const int m = m0 + wm * 64 + am * 16 + gid + hrow * 8;
                *(float2*)&Cz[(long)m * N + col] =
                    make_float2(c[am][an][hrow * 2 + 0], c[am][an][hrow * 2 + 1]);
            }
        }
}

// ---------------- split-K reduce + bias + silu --------------------------------
__global__ void reduce_silu_kernel(const float* __restrict__ part,
                                   const float* __restrict__ bias,
                                   float* __restrict__ out) {
    const long MN = (long)B_ * HEADH_;
    const long e = ((long)blockIdx.x * 256 + threadIdx.x) * 4;
    const int n = (int)(e % HEADH_);
    float4 a = *(const float4*)&part[e];
    #pragma unroll
    for (int z = 1; z < SPLITK; z++) {
        const float4 p = *(const float4*)&part[z * MN + e];
        a.x += p.x; a.y += p.y; a.z += p.z; a.w += p.w;
    }
    const float4 bi = *(const float4*)&bias[n];
    a.x += bi.x; a.y += bi.y; a.z += bi.z; a.w += bi.w;
    a.x = a.x / (1.f + expf(-a.x));
    a.y = a.y / (1.f + expf(-a.y));
    a.z = a.z / (1.f + expf(-a.z));
    a.w = a.w / (1.f + expf(-a.w));
    *(float4*)&out[e] = a;
}

// ---------------- fused attention per (b,h); out += attn ---------------------
__global__ __launch_bounds__(96)
void attn_kernel(const float* __restrict__ qkv, float* __restrict__ out) {
    const int h = blockIdx.x, b = blockIdx.y;
    __shared__ __align__(16) float Ks[T1_ * 32];
    __shared__ __align__(16) float Vs[T1_ * 32];
    __shared__ float S[T1_ * 67];
    const float* base = qkv + (long)b * T1_ * 768 + h * 96;

    for (int idx = threadIdx.x; idx < T1_ * 8; idx += 96) {
        int r = idx >> 3, c4 = (idx & 7) << 2;
        *(float4*)&Ks[r * 32 + c4] = *(const float4*)&base[r * 768 + 32 + c4];
        *(float4*)&Vs[r * 32 + c4] = *(const float4*)&base[r * 768 + 64 + c4];
    }
    __syncthreads();

    const int r = threadIdx.x;
    if (r < T1_) {
        float4 q4[8];
        #pragma unroll
        for (int j = 0; j < 8; j++)
            q4[j] = *(const float4*)&base[r * 768 + j * 4];

        float mx = -1e30f;
        for (int k = 0; k < T1_; k++) {
            float acc = 0.f;
            #pragma unroll
            for (int j = 0; j < 8; j++) {
                const float4 kv = *(const float4*)&Ks[k * 32 + j * 4];
                acc += q4[j].x * kv.x + q4[j].y * kv.y + q4[j].z * kv.z + q4[j].w * kv.w;
            }
            acc *= 0.17677669529663687f;
            S[r * 67 + k] = acc;
            mx = fmaxf(mx, acc);
        }
        float sum = 0.f;
        for (int k = 0; k < T1_; k++) {
            float e = expf(S[r * 67 + k] - mx);
            S[r * 67 + k] = e;
            sum += e;
        }
        const float inv = 1.f / sum;

        float4 acc4[8];
        #pragma unroll
        for (int j = 0; j < 8; j++) acc4[j] = make_float4(0.f, 0.f, 0.f, 0.f);
        for (int k = 0; k < T1_; k++) {
            const float s = S[r * 67 + k];
            #pragma unroll
            for (int j = 0; j < 8; j++) {
                const float4 vv = *(const float4*)&Vs[k * 32 + j * 4];
                acc4[j].x += s * vv.x; acc4[j].y += s * vv.y;
                acc4[j].z += s * vv.z; acc4[j].w += s * vv.w;
            }
        }
        float* op = out + ((long)b * T1_ + r) * D_ + h * HD_;
        #pragma unroll
        for (int j = 0; j < 8; j++) {
            float4 o = *(float4*)&op[j * 4];
            o.x += acc4[j].x * inv; o.y += acc4[j].y * inv;
            o.z += acc4[j].z * inv; o.w += acc4[j].w * inv;
            *(float4*)&op[j * 4] = o;
        }
    }
}

// ---------------- final classifier head --------------------------------------
__global__ void head2_kernel(const float* __restrict__ hid, const float* __restrict__ W2,
                             const float* __restrict__ b2, float* __restrict__ out) {
    int b = blockIdx.x;
    float acc[NCLS_] = {};
    for (int k = threadIdx.x; k < HEADH_; k += 256) {
        float hv = hid[(long)b * HEADH_ + k];
        #pragma unroll
        for (int c = 0; c < NCLS_; c++) acc[c] += hv * W2[k * NCLS_ + c];
    }
    __shared__ float red[256];
    for (int c = 0; c < NCLS_; c++) {
        red[threadIdx.x] = acc[c];
        __syncthreads();
        for (int o = 128; o > 0; o >>= 1) {
            if (threadIdx.x < o) red[threadIdx.x] += red[threadIdx.x + o];
            __syncthreads();
        }
        if (threadIdx.x == 0) out[b * NCLS_ + c] = red[0] + b2[c];
        __syncthreads();
    }
}

// -----------------------------------------------------------------------------
extern "C" void kernel_launch(void* const* d_in, const int* in_sizes, int n_in,
                              void* d_out, int out_size) {
    const float* x      = (const float*)d_in[0];
    const float* cls    = (const float*)d_in[1];
    const float* Wp     = (const float*)d_in[2];
    const float* bp     = (const float*)d_in[3];
    const float* qkv_w  = (const float*)d_in[4];
    const float* qkv_b  = (const float*)d_in[5];
    const float* ln_w   = (const float*)d_in[6];
    const float* ln_b   = (const float*)d_in[7];
    const float* mlp1_w = (const float*)d_in[8];
    const float* mlp1_b = (const float*)d_in[9];
    const float* mlp2_w = (const float*)d_in[10];
    const float* mlp2_b = (const float*)d_in[11];
    const float* h1w    = (const float*)d_in[12];
    const float* h1b    = (const float*)d_in[13];
    const float* h2w    = (const float*)d_in[14];
    const float* h2b    = (const float*)d_in[15];
    float* out = (float*)d_out;

    float *p_out, *p_qkv, *p_hid, *p_part;
    bf16 *p_hh, *p_hl, *p_mh, *p_ml, *p_wqh, *p_wql, *p_w1h, *p_w1l, *p_w2h, *p_w2l;
    cudaGetSymbolAddress((void**)&p_out, g_out);
    cudaGetSymbolAddress((void**)&p_qkv, g_qkv);
    cudaGetSymbolAddress((void**)&p_hid, g_hid);
    cudaGetSymbolAddress((void**)&p_part, g_part);
    cudaGetSymbolAddress((void**)&p_hh, g_hh);
    cudaGetSymbolAddress((void**)&p_hl, g_hl);
    cudaGetSymbolAddress((void**)&p_mh, g_mh);
    cudaGetSymbolAddress((void**)&p_ml, g_ml);
    cudaGetSymbolAddress((void**)&p_wqh, g_wqh);
    cudaGetSymbolAddress((void**)&p_wql, g_wql);
    cudaGetSymbolAddress((void**)&p_w1h, g_w1h);
    cudaGetSymbolAddress((void**)&p_w1l, g_w1l);
    cudaGetSymbolAddress((void**)&p_w2h, g_w2h);
    cudaGetSymbolAddress((void**)&p_w2l, g_w2l);

    cudaFuncSetAttribute(gemm_fast<0,false,false>, cudaFuncAttributeMaxDynamicSharedMemorySize, GSMEM_TOTAL);
    cudaFuncSetAttribute(gemm_fast<1,false,true>,  cudaFuncAttributeMaxDynamicSharedMemorySize, GSMEM_TOTAL);
    cudaFuncSetAttribute(gemm_fast<0,true,false>,  cudaFuncAttributeMaxDynamicSharedMemorySize, GSMEM_TOTAL);
    cudaFuncSetAttribute(gemm_h1, cudaFuncAttributeMaxDynamicSharedMemorySize, GSMEM_TOTAL);

    // weight preconversion (transposed bf16 hi/lo planes)
    for (int l = 0; l < 2; l++) {
        convert_wt_kernel<<<(768 * (D_/8) + 255)/256, 256>>>(
            qkv_w + l * D_ * 768, p_wqh + (long)l * 768 * D_, p_wql + (long)l * 768 * D_, D_, 768);
        convert_wt_kernel<<<(MLPH_ * (D_/8) + 255)/256, 256>>>(
            mlp1_w + l * D_ * MLPH_, p_w1h + (long)l * MLPH_ * D_, p_w1l + (long)l * MLPH_ * D_, D_, MLPH_);
        convert_wt_kernel<<<(D_ * (MLPH_/8) + 255)/256, 256>>>(
            mlp2_w + l * MLPH_ * D_, p_w2h + (long)l * D_ * MLPH_, p_w2l + (long)l * D_ * MLPH_, MLPH_, D_);
    }

    dim3 gPatch(B_, T1_);
    patch_embed_kernel<<<gPatch, 256>>>(x, cls, Wp, bp, p_out);

    const int Mt = B_ * T1_;   // 16640
    for (int l = 0; l < 2; l++) {
        ln2d_split_kernel<<<B_, 256>>>(p_out, ln_w + l * ND_, ln_b + l * ND_, p_hh, p_hl);
        gemm_fast<0,false,false><<<dim3(768/128, Mt/256), 512, GSMEM_TOTAL>>>(
            p_hh, p_hl, p_wqh + (long)l * 768 * D_, p_wql + (long)l * 768 * D_,
            qkv_b + l * 768, nullptr, p_qkv, nullptr, nullptr, Mt, 768, D_);
        attn_kernel<<<dim3(H_, B_), 96>>>(p_qkv, p_out);
        ln2d_split_kernel<<<B_, 256>>>(p_out, ln_w + l * ND_, ln_b + l * ND_, p_hh, p_hl);
        gemm_fast<1,false,true><<<dim3(MLPH_/128, Mt/256), 512, GSMEM_TOTAL>>>(
            p_hh, p_hl, p_w1h + (long)l * MLPH_ * D_, p_w1l + (long)l * MLPH_ * D_,
            mlp1_b + l * MLPH_, nullptr, nullptr, p_mh, p_ml, Mt, MLPH_, D_);
        gemm_fast<0,true,false><<<dim3(D_/128, Mt/256), 512, GSMEM_TOTAL>>>(
            p_mh, p_ml, p_w2h + (long)l * D_ * MLPH_, p_w2l + (long)l * D_ * MLPH_,
            mlp2_b + l * D_, p_out, p_out, nullptr, nullptr, Mt, D_, MLPH_);
    }

    // head1: split p_out into planes, then split-K GEMM + fused reduce
    split_plane_kernel<<<(ND_ * B_ / 4 + 255)/256, 256>>>(p_out, p_hh, p_hl, (long)ND_ * B_);
    gemm_h1<<<dim3(HEADH_/128, B_/256, SPLITK), 512, GSMEM_TOTAL>>>(
        p_hh, p_hl, h1w, p_part, B_, HEADH_, ND_, KCHUNK);
    reduce_silu_kernel<<<(B_ * HEADH_)/1024, 256>>>(p_part, h1b, p_hid);

    head2_kernel<<<B_, 256>>>(p_hid, h2w, h2b, out);
}

// round 12
// speedup vs baseline: 1.1396x; 1.1396x over previous
#include <cuda_runtime.h>
#include <cuda_fp16.h>
#include <math.h>
#include <stdint.h>

#define B_    256
#define C_    3
#define IMG_  32
#define D_    256
#define H_    8
#define HD_   32
#define T1_   65
#define MLPH_ 2048
#define HEADH_ 8192
#define NCLS_ 10
#define PDIM_ 48
#define ND_   (T1_*D_)   // 16640
#define SPLITK 4
#define KCHUNK (ND_/SPLITK)   // 4160

// ---------------- scratch ----------------------------------------------------
__device__ float g_out[B_*T1_*D_];
__device__ float g_h[B_*T1_*D_];
__device__ float g_qkv[B_*T1_*3*D_];
__device__ float g_m[B_*T1_*MLPH_];
__device__ float g_hid[B_*HEADH_];
__device__ float g_part[SPLITK*B_*HEADH_];

// ---------------- patch embed + cls + positional encoding --------------------
__global__ void patch_embed_kernel(const float* __restrict__ x,
                                   const float* __restrict__ cls,
                                   const float* __restrict__ Wp,
                                   const float* __restrict__ bp,
                                   float* __restrict__ out) {
    int b = blockIdx.x;
    int t = blockIdx.y;
    int d = threadIdx.x;
    int i = d >> 1;
    float div = expf(-(float)(2 * i) * (9.210340371976184f / 256.0f));
    float ang = (float)t * div;
    float pe = (d & 1) ? cosf(ang) : sinf(ang);

    if (t == 0) {
        out[(b * T1_) * D_ + d] = cls[d] + pe;
    } else {
        __shared__ float sp[PDIM_];
        int tt = t - 1;
        int ni = tt >> 3, nj = tt & 7;
        if (d < PDIM_) {
            int c  = d / 16;
            int pi = (d >> 2) & 3;
            int pj = d & 3;
            sp[d] = x[((b * C_ + c) * IMG_ + ni * 4 + pi) * IMG_ + nj * 4 + pj];
        }
        __syncthreads();
        float acc = bp[d];
        #pragma unroll
        for (int k = 0; k < PDIM_; k++) acc += sp[k] * Wp[k * D_ + d];
        out[((b * T1_) + t) * D_ + d] = acc + pe;
    }
}

// ---------------- LayerNorm over whole (T1,D) slab per sample ----------------
__global__ void ln2d_kernel(const float* __restrict__ X,
                            const float* __restrict__ w,
                            const float* __restrict__ bb,
                            float* __restrict__ Y) {
    int b = blockIdx.x;
    const float* xb = X + b * ND_;
    float s = 0.f, s2 = 0.f;
    for (int i = threadIdx.x; i < ND_; i += 256) {
        float v = xb[i];
        s += v; s2 += v * v;
    }
    __shared__ float rs[8], rs2[8], bc[2];
    #pragma unroll
    for (int o = 16; o > 0; o >>= 1) {
        s  += __shfl_down_sync(0xffffffffu, s,  o);
        s2 += __shfl_down_sync(0xffffffffu, s2, o);
    }
    int wid = threadIdx.x >> 5, lid = threadIdx.x & 31;
    if (lid == 0) { rs[wid] = s; rs2[wid] = s2; }
    __syncthreads();
    if (threadIdx.x == 0) {
        float ts = 0.f, ts2 = 0.f;
        #pragma unroll
        for (int k = 0; k < 8; k++) { ts += rs[k]; ts2 += rs2[k]; }
        float mu  = ts / (float)ND_;
        float var = ts2 / (float)ND_ - mu * mu;
        bc[0] = mu;
        bc[1] = rsqrtf(var + 1e-5f);
    }
    __syncthreads();
    float mu = bc[0], rsg = bc[1];
    float* yb = Y + b * ND_;
    for (int i = threadIdx.x; i < ND_; i += 256) {
        yb[i] = (xb[i] - mu) * rsg * w[i] + bb[i];
    }
}

// ---------------- fp16 2-term tensor-core GEMM (mma.sync m16n8k16) -----------
// C(M,N) = act(A(M,K) @ W(K,N) + bias) (+R).
// A -> fp16 (hi only); W -> fp16 hi + lo. C = Ah*Wh + Ah*Wl, fp32 accumulate.
// CTA tile 256x128, BK=32, 512 threads (16 warps), warp tile 64x32.
// ACT: 0 none, 1 relu, 2 silu, 3 raw partial (split-K, z-offset output)
#define PITCH 40
#define SA_H 0
#define SB_H 20480
#define SB_L 30720
#define BUFSZ 40960
#define GSMEM_TOTAL (2*BUFSZ)

__device__ __forceinline__ void mma16816h(float* c, const uint32_t* a, const uint32_t* b) {
    asm volatile(
        "mma.sync.aligned.m16n8k16.row.col.f32.f16.f16.f32 "
        "{%0,%1,%2,%3}, {%4,%5,%6,%7}, {%8,%9}, {%0,%1,%2,%3};"
        : "+f"(c[0]), "+f"(c[1]), "+f"(c[2]), "+f"(c[3])
        : "r"(a[0]), "r"(a[1]), "r"(a[2]), "r"(a[3]), "r"(b[0]), "r"(b[1]));
}
__device__ __forceinline__ void split_pair_h(float x, float y, __half2& hi, __half2& lo) {
    hi = __floats2half2_rn(x, y);
    float2 hf = __half22float2(hi);
    lo = __floats2half2_rn(x - hf.x, y - hf.y);
}

template<int ACT, bool RES>
__global__ void __launch_bounds__(512, 1) gemm_tc(
    const float* __restrict__ A, const float* __restrict__ W,
    const float* __restrict__ bias, const float* __restrict__ R,
    float* __restrict__ Cc, int M, int N, int K, int kChunk)
{
    extern __shared__ char smem[];
    const int tid = threadIdx.x;
    const int wid = tid >> 5;
    const int lane = tid & 31;
    const int wm = wid >> 2, wn = wid & 3;       // 4x4 warps -> 64x32 tiles
    const int m0 = blockIdx.y * 256, n0 = blockIdx.x * 128;
    const int kbase = blockIdx.z * kChunk;
    float* Cz = Cc + (long)blockIdx.z * M * N;
    const int gid = lane >> 2, tig = lane & 3;

    const int bn = tid & 127;
    const int bkh = (tid >> 7) * 8;              // 4 groups x 8 k-values

    float c[4][4][4];
    #pragma unroll
    for (int i = 0; i < 4; i++)
        #pragma unroll
        for (int j = 0; j < 4; j++)
            #pragma unroll
            for (int r = 0; r < 4; r++) c[i][j][r] = 0.f;

    const int nk = kChunk / 32;
    float4 ra[4];
    float rb[8];

    auto ldg_tile = [&](int t) {
        #pragma unroll
        for (int i = 0; i < 4; i++) {
            int lin = tid + i * 512;
            int row = lin >> 3, q = lin & 7;
            ra[i] = *(const float4*)&A[(long)(m0 + row) * K + kbase + t * 32 + q * 4];
        }
        const float* Wb = W + (long)(kbase + t * 32 + bkh) * N + n0 + bn;
        #pragma unroll
        for (int p = 0; p < 8; p++) rb[p] = Wb[(long)p * N];
    };
    auto sts_tile = [&](int buf) {
        char* base = smem + buf * BUFSZ;
        #pragma unroll
        for (int i = 0; i < 4; i++) {
            int lin = tid + i * 512;
            int row = lin >> 3, q = lin & 7;
            __half2 h0 = __floats2half2_rn(ra[i].x, ra[i].y);
            __half2 h1 = __floats2half2_rn(ra[i].z, ra[i].w);
            int e = row * PITCH + q * 4;
            *(__half2*)(base + SA_H + e * 2)     = h0;
            *(__half2*)(base + SA_H + e * 2 + 4) = h1;
        }
        #pragma unroll
        for (int p = 0; p < 4; p++) {
            __half2 h, l;
            split_pair_h(rb[2 * p], rb[2 * p + 1], h, l);
            int e = bn * PITCH + bkh + 2 * p;
            *(__half2*)(base + SB_H + e * 2) = h;
            *(__half2*)(base + SB_L + e * 2) = l;
        }
    };

    ldg_tile(0);
    sts_tile(0);
    __syncthreads();

    for (int t = 0; t < nk; t++) {
        const int buf = t & 1;
        if (t + 1 < nk) ldg_tile(t + 1);

        const char* ahp = smem + buf * BUFSZ + SA_H;
        const char* bhp = smem + buf * BUFSZ + SB_H;
        const char* blp = smem + buf * BUFSZ + SB_L;

        #pragma unroll
        for (int ks = 0; ks < 2; ks++) {
            const int acol = ks * 16 + tig * 2;
            uint32_t bh[4][2], bl[4][2];
            #pragma unroll
            for (int an = 0; an < 4; an++) {
                const int brow = wn * 32 + an * 8 + gid;
                const int e = (brow * PITCH + acol) * 2;
                bh[an][0] = *(const uint32_t*)(bhp + e);
                bh[an][1] = *(const uint32_t*)(bhp + e + 16);
                bl[an][0] = *(const uint32_t*)(blp + e);
                bl[an][1] = *(const uint32_t*)(blp + e + 16);
            }
            #pragma unroll
            for (int am = 0; am < 4; am++) {
                const int arow = wm * 64 + am * 16 + gid;
                const int e00 = (arow * PITCH + acol) * 2;
                const int e10 = ((arow + 8) * PITCH + acol) * 2;
                uint32_t ah[4];
                ah[0] = *(const uint32_t*)(ahp + e00);
                ah[1] = *(const uint32_t*)(ahp + e10);
                ah[2] = *(const uint32_t*)(ahp + e00 + 16);
                ah[3] = *(const uint32_t*)(ahp + e10 + 16);
                #pragma unroll
                for (int an = 0; an < 4; an++) {
                    mma16816h(c[am][an], ah, bh[an]);
                    mma16816h(c[am][an], ah, bl[an]);
                }
            }
        }

        if (t + 1 < nk) sts_tile(buf ^ 1);
        __syncthreads();
    }

    // ---- epilogue ----
    #pragma unroll
    for (int am = 0; am < 4; am++) {
        #pragma unroll
        for (int an = 0; an < 4; an++) {
            const int col = n0 + wn * 32 + an * 8 + tig * 2;
            float bx = 0.f, by = 0.f;
            if (ACT != 3) { bx = bias[col]; by = bias[col + 1]; }
            #pragma unroll
            for (int hrow = 0; hrow < 2; hrow++) {
                const int m = m0 + wm * 64 + am * 16 + gid + hrow * 8;
                float vx = c[am][an][hrow * 2 + 0] + bx;
                float vy = c[am][an][hrow * 2 + 1] + by;
                if (ACT == 1) { vx = fmaxf(vx, 0.f); vy = fmaxf(vy, 0.f); }
                if (ACT == 2) {
                    vx = vx / (1.f + expf(-vx));
                    vy = vy / (1.f + expf(-vy));
                }
                if (RES) {
                    const float2 r2 = *(const float2*)&R[(long)m * N + col];
                    vx += r2.x; vy += r2.y;
                }
                *(float2*)&Cz[(long)m * N + col] = make_float2(vx, vy);
            }
        }
    }
}

// ---------------- split-K reduce + bias + silu --------------------------------
__global__ void reduce_silu_kernel(const float* __restrict__ part,
                                   const float* __restrict__ bias,
                                   float* __restrict__ out) {
    const long MN = (long)B_ * HEADH_;
    const long e = ((long)blockIdx.x * 256 + threadIdx.x) * 4;
    const int n = (int)(e % HEADH_);
    float4 a = *(const float4*)&part[e];
    #pragma unroll
    for (int z = 1; z < SPLITK; z++) {
        const float4 p = *(const float4*)&part[z * MN + e];
        a.x += p.x; a.y += p.y; a.z += p.z; a.w += p.w;
    }
    const float4 bi = *(const float4*)&bias[n];
    a.x += bi.x; a.y += bi.y; a.z += bi.z; a.w += bi.w;
    a.x = a.x / (1.f + expf(-a.x));
    a.y = a.y / (1.f + expf(-a.y));
    a.z = a.z / (1.f + expf(-a.z));
    a.w = a.w / (1.f + expf(-a.w));
    *(float4*)&out[e] = a;
}

// ---------------- fused attention per (b,h); out += attn ---------------------
__global__ __launch_bounds__(96)
void attn_kernel(const float* __restrict__ qkv, float* __restrict__ out) {
    const int h = blockIdx.x, b = blockIdx.y;
    __shared__ __align__(16) float Ks[T1_ * 32];
    __shared__ __align__(16) float Vs[T1_ * 32];
    __shared__ float S[T1_ * 67];
    const float* base = qkv + (long)b * T1_ * 768 + h * 96;

    for (int idx = threadIdx.x; idx < T1_ * 8; idx += 96) {
        int r = idx >> 3, c4 = (idx & 7) << 2;
        *(float4*)&Ks[r * 32 + c4] = *(const float4*)&base[r * 768 + 32 + c4];
        *(float4*)&Vs[r * 32 + c4] = *(const float4*)&base[r * 768 + 64 + c4];
    }
    __syncthreads();

    const int r = threadIdx.x;
    if (r < T1_) {
        float4 q4[8];
        #pragma unroll
        for (int j = 0; j < 8; j++)
            q4[j] = *(const float4*)&base[r * 768 + j * 4];

        float mx = -1e30f;
        for (int k = 0; k < T1_; k++) {
            float acc = 0.f;
            #pragma unroll
            for (int j = 0; j < 8; j++) {
                const float4 kv = *(const float4*)&Ks[k * 32 + j * 4];
                acc += q4[j].x * kv.x + q4[j].y * kv.y + q4[j].z * kv.z + q4[j].w * kv.w;
            }
            acc *= 0.17677669529663687f;
            S[r * 67 + k] = acc;
            mx = fmaxf(mx, acc);
        }
        float sum = 0.f;
        for (int k = 0; k < T1_; k++) {
            float e = expf(S[r * 67 + k] - mx);
            S[r * 67 + k] = e;
            sum += e;
        }
        const float inv = 1.f / sum;

        float4 acc4[8];
        #pragma unroll
        for (int j = 0; j < 8; j++) acc4[j] = make_float4(0.f, 0.f, 0.f, 0.f);
        for (int k = 0; k < T1_; k++) {
            const float s = S[r * 67 + k];
            #pragma unroll
            for (int j = 0; j < 8; j++) {
                const float4 vv = *(const float4*)&Vs[k * 32 + j * 4];
                acc4[j].x += s * vv.x; acc4[j].y += s * vv.y;
                acc4[j].z += s * vv.z; acc4[j].w += s * vv.w;
            }
        }
        float* op = out + ((long)b * T1_ + r) * D_ + h * HD_;
        #pragma unroll
        for (int j = 0; j < 8; j++) {
            float4 o = *(float4*)&op[j * 4];
            o.x += acc4[j].x * inv; o.y += acc4[j].y * inv;
            o.z += acc4[j].z * inv; o.w += acc4[j].w * inv;
            *(float4*)&op[j * 4] = o;
        }
    }
}

// ---------------- final classifier head --------------------------------------
__global__ void head2_kernel(const float* __restrict__ hid, const float* __restrict__ W2,
                             const float* __restrict__ b2, float* __restrict__ out) {
    int b = blockIdx.x;
    float acc[NCLS_] = {};
    for (int k = threadIdx.x; k < HEADH_; k += 256) {
        float hv = hid[(long)b * HEADH_ + k];
        #pragma unroll
        for (int c = 0; c < NCLS_; c++) acc[c] += hv * W2[k * NCLS_ + c];
    }
    __shared__ float red[256];
    for (int c = 0; c < NCLS_; c++) {
        red[threadIdx.x] = acc[c];
        __syncthreads();
        for (int o = 128; o > 0; o >>= 1) {
            if (threadIdx.x < o) red[threadIdx.x] += red[threadIdx.x + o];
            __syncthreads();
        }
        if (threadIdx.x == 0) out[b * NCLS_ + c] = red[0] + b2[c];
        __syncthreads();
    }
}

// -----------------------------------------------------------------------------
extern "C" void kernel_launch(void* const* d_in, const int* in_sizes, int n_in,
                              void* d_out, int out_size) {
    const float* x      = (const float*)d_in[0];
    const float* cls    = (const float*)d_in[1];
    const float* Wp     = (const float*)d_in[2];
    const float* bp     = (const float*)d_in[3];
    const float* qkv_w  = (const float*)d_in[4];
    const float* qkv_b  = (const float*)d_in[5];
    const float* ln_w   = (const float*)d_in[6];
    const float* ln_b   = (const float*)d_in[7];
    const float* mlp1_w = (const float*)d_in[8];
    const float* mlp1_b = (const float*)d_in[9];
    const float* mlp2_w = (const float*)d_in[10];
    const float* mlp2_b = (const float*)d_in[11];
    const float* h1w    = (const float*)d_in[12];
    const float* h1b    = (const float*)d_in[13];
    const float* h2w    = (const float*)d_in[14];
    const float* h2b    = (const float*)d_in[15];
    float* out = (float*)d_out;

    float *p_out, *p_h, *p_qkv, *p_m, *p_hid, *p_part;
    cudaGetSymbolAddress((void**)&p_out, g_out);
    cudaGetSymbolAddress((void**)&p_h,   g_h);
    cudaGetSymbolAddress((void**)&p_qkv, g_qkv);
    cudaGetSymbolAddress((void**)&p_m,   g_m);
    cudaGetSymbolAddress((void**)&p_hid, g_hid);
    cudaGetSymbolAddress((void**)&p_part, g_part);

    cudaFuncSetAttribute(gemm_tc<0,false>, cudaFuncAttributeMaxDynamicSharedMemorySize, GSMEM_TOTAL);
    cudaFuncSetAttribute(gemm_tc<1,false>, cudaFuncAttributeMaxDynamicSharedMemorySize, GSMEM_TOTAL);
    cudaFuncSetAttribute(gemm_tc<0,true>,  cudaFuncAttributeMaxDynamicSharedMemorySize, GSMEM_TOTAL);
    cudaFuncSetAttribute(gemm_tc<3,false>, cudaFuncAttributeMaxDynamicSharedMemorySize, GSMEM_TOTAL);

    dim3 gPatch(B_, T1_);
    patch_embed_kernel<<<gPatch, 256>>>(x, cls, Wp, bp, p_out);

    const int Mt = B_ * T1_;   // 16640 rows, /256 = 65 m-tiles
    for (int l = 0; l < 2; l++) {
        ln2d_kernel<<<B_, 256>>>(p_out, ln_w + l * ND_, ln_b + l * ND_, p_h);
        gemm_tc<0, false><<<dim3(768 / 128, Mt / 256), 512, GSMEM_TOTAL>>>(
            p_h, qkv_w + l * D_ * 768, qkv_b + l * 768, nullptr, p_qkv,
            Mt, 768, D_, D_);
        attn_kernel<<<dim3(H_, B_), 96>>>(p_qkv, p_out);
        ln2d_kernel<<<B_, 256>>>(p_out, ln_w + l * ND_, ln_b + l * ND_, p_h);
        gemm_tc<1, false><<<dim3(MLPH_ / 128, Mt / 256), 512, GSMEM_TOTAL>>>(
            p_h, mlp1_w + l * D_ * MLPH_, mlp1_b + l * MLPH_, nullptr, p_m,
            Mt, MLPH_, D_, D_);
        gemm_tc<0, true><<<dim3(D_ / 128, Mt / 256), 512, GSMEM_TOTAL>>>(
            p_m, mlp2_w + l * MLPH_ * D_, mlp2_b + l * D_, p_out, p_out,
            Mt, D_, MLPH_, MLPH_);
    }

    // head1 split-K: partials then fused reduce+bias+silu
    gemm_tc<3, false><<<dim3(HEADH_ / 128, B_ / 256, SPLITK), 512, GSMEM_TOTAL>>>(
        p_out, h1w, h1b, nullptr, p_part, B_, HEADH_, ND_, KCHUNK);
    reduce_silu_kernel<<<(B_ * HEADH_) / 1024, 256>>>(p_part, h1b, p_hid);

    head2_kernel<<<B_, 256>>>(p_hid, h2w, h2b, out);
}

// round 13
// speedup vs baseline: 1.2273x; 1.0770x over previous
#include <cuda_runtime.h>
#include <cuda_fp16.h>
#include <math.h>
#include <stdint.h>

#define B_    256
#define C_    3
#define IMG_  32
#define D_    256
#define H_    8
#define HD_   32
#define T1_   65
#define MLPH_ 2048
#define HEADH_ 8192
#define NCLS_ 10
#define PDIM_ 48
#define ND_   (T1_*D_)   // 16640
#define SPLITK 4
#define KCHUNK (ND_/SPLITK)   // 4160

// ---------------- scratch ----------------------------------------------------
__device__ float g_out[B_*T1_*D_];
__device__ float g_h[B_*T1_*D_];
__device__ float g_qkv[B_*T1_*3*D_];
__device__ float g_m[B_*T1_*MLPH_];
__device__ float g_hid[B_*HEADH_];
__device__ float g_part[SPLITK*B_*HEADH_];

// ---------------- patch embed + cls + positional encoding --------------------
__global__ void patch_embed_kernel(const float* __restrict__ x,
                                   const float* __restrict__ cls,
                                   const float* __restrict__ Wp,
                                   const float* __restrict__ bp,
                                   float* __restrict__ out) {
    int b = blockIdx.x;
    int t = blockIdx.y;
    int d = threadIdx.x;
    int i = d >> 1;
    float div = expf(-(float)(2 * i) * (9.210340371976184f / 256.0f));
    float ang = (float)t * div;
    float pe = (d & 1) ? cosf(ang) : sinf(ang);

    if (t == 0) {
        out[(b * T1_) * D_ + d] = cls[d] + pe;
    } else {
        __shared__ float sp[PDIM_];
        int tt = t - 1;
        int ni = tt >> 3, nj = tt & 7;
        if (d < PDIM_) {
            int c  = d / 16;
            int pi = (d >> 2) & 3;
            int pj = d & 3;
            sp[d] = x[((b * C_ + c) * IMG_ + ni * 4 + pi) * IMG_ + nj * 4 + pj];
        }
        __syncthreads();
        float acc = bp[d];
        #pragma unroll
        for (int k = 0; k < PDIM_; k++) acc += sp[k] * Wp[k * D_ + d];
        out[((b * T1_) + t) * D_ + d] = acc + pe;
    }
}

// ---------------- LayerNorm over whole (T1,D) slab per sample ----------------
__global__ void ln2d_kernel(const float* __restrict__ X,
                            const float* __restrict__ w,
                            const float* __restrict__ bb,
                            float* __restrict__ Y) {
    int b = blockIdx.x;
    const float* xb = X + b * ND_;
    float s = 0.f, s2 = 0.f;
    for (int i = threadIdx.x; i < ND_; i += 256) {
        float v = xb[i];
        s += v; s2 += v * v;
    }
    __shared__ float rs[8], rs2[8], bc[2];
    #pragma unroll
    for (int o = 16; o > 0; o >>= 1) {
        s  += __shfl_down_sync(0xffffffffu, s,  o);
        s2 += __shfl_down_sync(0xffffffffu, s2, o);
    }
    int wid = threadIdx.x >> 5, lid = threadIdx.x & 31;
    if (lid == 0) { rs[wid] = s; rs2[wid] = s2; }
    __syncthreads();
    if (threadIdx.x == 0) {
        float ts = 0.f, ts2 = 0.f;
        #pragma unroll
        for (int k = 0; k < 8; k++) { ts += rs[k]; ts2 += rs2[k]; }
        float mu  = ts / (float)ND_;
        float var = ts2 / (float)ND_ - mu * mu;
        bc[0] = mu;
        bc[1] = rsqrtf(var + 1e-5f);
    }
    __syncthreads();
    float mu = bc[0], rsg = bc[1];
    float* yb = Y + b * ND_;
    for (int i = threadIdx.x; i < ND_; i += 256) {
        yb[i] = (xb[i] - mu) * rsg * w[i] + bb[i];
    }
}

// ---------------- fp16 2-term tensor-core GEMM, BK=64 ------------------------
// C(M,N) = act(A(M,K) @ W(K,N) + bias) (+R).
// A -> fp16 hi only; W -> fp16 hi + lo. C = Ah*Wh + Ah*Wl, fp32 accumulate.
// CTA tile 256x128, BK=64, 512 threads (16 warps), warp tile 64x32.
// ACT: 0 none, 1 relu, 2 silu, 3 raw partial (split-K, z-offset output)
#define PITCH 72                      // fp16 elements per smem row (64 + 8 pad)
#define SA_H 0                        // 256*72*2 = 36864
#define SB_H 36864                    // 128*72*2 = 18432
#define SB_L 55296
#define BUFSZ 73728
#define GSMEM_TOTAL (2*BUFSZ)         // 147456

__device__ __forceinline__ void mma16816h(float* c, const uint32_t* a, const uint32_t* b) {
    asm volatile(
        "mma.sync.aligned.m16n8k16.row.col.f32.f16.f16.f32 "
        "{%0,%1,%2,%3}, {%4,%5,%6,%7}, {%8,%9}, {%0,%1,%2,%3};"
        : "+f"(c[0]), "+f"(c[1]), "+f"(c[2]), "+f"(c[3])
        : "r"(a[0]), "r"(a[1]), "r"(a[2]), "r"(a[3]), "r"(b[0]), "r"(b[1]));
}
__device__ __forceinline__ void split_pair_h(float x, float y, __half2& hi, __half2& lo) {
    hi = __floats2half2_rn(x, y);
    float2 hf = __half22float2(hi);
    lo = __floats2half2_rn(x - hf.x, y - hf.y);
}

template<int ACT, bool RES>
__global__ void __launch_bounds__(512, 1) gemm_tc(
    const float* __restrict__ A, const float* __restrict__ W,
    const float* __restrict__ bias, const float* __restrict__ R,
    float* __restrict__ Cc, int M, int N, int K, int kChunk)
{
    extern __shared__ char smem[];
    const int tid = threadIdx.x;
    const int wid = tid >> 5;
    const int lane = tid & 31;
    const int wm = wid >> 2, wn = wid & 3;       // 4x4 warps -> 64x32 tiles
    const int m0 = blockIdx.y * 256, n0 = blockIdx.x * 128;
    const int kbase = blockIdx.z * kChunk;
    float* Cz = Cc + (long)blockIdx.z * M * N;
    const int gid = lane >> 2, tig = lane & 3;

    const int bn = tid & 127;                    // W fill: n index
    const int bkh = (tid >> 7) * 16;             // W fill: k group of 16

    float c[4][4][4];
    #pragma unroll
    for (int i = 0; i < 4; i++)
        #pragma unroll
        for (int j = 0; j < 4; j++)
            #pragma unroll
            for (int r = 0; r < 4; r++) c[i][j][r] = 0.f;

    const int nk = kChunk / 64;
    // prefetch regs, already converted to fp16
    uint32_t rah[16];                 // A hi: 8 float4 -> 16 half2
    uint32_t rwh[8], rwl[8];          // W hi/lo: 16 floats -> 8+8 half2

    const int ar = tid >> 4, aq = tid & 15;      // A fill: 16 float4 per row

    auto ldg_tile = [&](int t) {
        #pragma unroll
        for (int i = 0; i < 8; i++) {
            int lin = tid + i * 512;
            int row = lin >> 4, q = lin & 15;
            float4 v = *(const float4*)&A[(long)(m0 + row) * K + kbase + t * 64 + q * 4];
            __half2 h0 = __floats2half2_rn(v.x, v.y);
            __half2 h1 = __floats2half2_rn(v.z, v.w);
            rah[2 * i]     = *(uint32_t*)&h0;
            rah[2 * i + 1] = *(uint32_t*)&h1;
        }
        const float* Wb = W + (long)(kbase + t * 64 + bkh) * N + n0 + bn;
        #pragma unroll
        for (int p = 0; p < 8; p++) {
            float w0 = Wb[(long)(2 * p) * N];
            float w1 = Wb[(long)(2 * p + 1) * N];
            __half2 h, l;
            split_pair_h(w0, w1, h, l);
            rwh[p] = *(uint32_t*)&h;
            rwl[p] = *(uint32_t*)&l;
        }
    };
    auto sts_tile = [&](int buf) {
        char* base = smem + buf * BUFSZ;
        #pragma unroll
        for (int i = 0; i < 8; i++) {
            int lin = tid + i * 512;
            int row = lin >> 4, q = lin & 15;
            int e = row * PITCH + q * 4;
            *(uint2*)(base + SA_H + e * 2) = make_uint2(rah[2 * i], rah[2 * i + 1]);
        }
        #pragma unroll
        for (int p = 0; p < 8; p++) {
            int e = bn * PITCH + bkh + 2 * p;
            *(uint32_t*)(base + SB_H + e * 2) = rwh[p];
            *(uint32_t*)(base + SB_L + e * 2) = rwl[p];
        }
    };

    ldg_tile(0);
    sts_tile(0);
    __syncthreads();

    for (int t = 0; t < nk; t++) {
        const int buf = t & 1;
        if (t + 1 < nk) ldg_tile(t + 1);

        const char* ahp = smem + buf * BUFSZ + SA_H;
        const char* bhp = smem + buf * BUFSZ + SB_H;
        const char* blp = smem + buf * BUFSZ + SB_L;

        #pragma unroll
        for (int ks = 0; ks < 4; ks++) {
            const int acol = ks * 16 + tig * 2;
            uint32_t bh[4][2], bl[4][2];
            #pragma unroll
            for (int an = 0; an < 4; an++) {
                const int brow = wn * 32 + an * 8 + gid;
                const int e = (brow * PITCH + acol) * 2;
                bh[an][0] = *(const uint32_t*)(bhp + e);
                bh[an][1] = *(const uint32_t*)(bhp + e + 16);
                bl[an][0] = *(const uint32_t*)(blp + e);
                bl[an][1] = *(const uint32_t*)(blp + e + 16);
            }
            #pragma unroll
            for (int am = 0; am < 4; am++) {
                const int arow = wm * 64 + am * 16 + gid;
                const int e00 = (arow * PITCH + acol) * 2;
                const int e10 = ((arow + 8) * PITCH + acol) * 2;
                uint32_t ah[4];
                ah[0] = *(const uint32_t*)(ahp + e00);
                ah[1] = *(const uint32_t*)(ahp + e10);
                ah[2] = *(const uint32_t*)(ahp + e00 + 16);
                ah[3] = *(const uint32_t*)(ahp + e10 + 16);
                #pragma unroll
                for (int an = 0; an < 4; an++) {
                    mma16816h(c[am][an], ah, bh[an]);
                    mma16816h(c[am][an], ah, bl[an]);
                }
            }
        }

        if (t + 1 < nk) sts_tile(buf ^ 1);
        __syncthreads();
    }

    // ---- epilogue ----
    #pragma unroll
    for (int am = 0; am < 4; am++) {
        #pragma unroll
        for (int an = 0; an < 4; an++) {
            const int col = n0 + wn * 32 + an * 8 + tig * 2;
            float bx = 0.f, by = 0.f;
            if (ACT != 3) { bx = bias[col]; by = bias[col + 1]; }
            #pragma unroll
            for (int hrow = 0; hrow < 2; hrow++) {
                const int m = m0 + wm * 64 + am * 16 + gid + hrow * 8;
                float vx = c[am][an][hrow * 2 + 0] + bx;
                float vy = c[am][an][hrow * 2 + 1] + by;
                if (ACT == 1) { vx = fmaxf(vx, 0.f); vy = fmaxf(vy, 0.f); }
                if (ACT == 2) {
                    vx = vx / (1.f + expf(-vx));
                    vy = vy / (1.f + expf(-vy));
                }
                if (RES) {
                    const float2 r2 = *(const float2*)&R[(long)m * N + col];
                    vx += r2.x; vy += r2.y;
                }
                *(float2*)&Cz[(long)m * N + col] = make_float2(vx, vy);
            }
        }
    }
}

// ---------------- split-K reduce + bias + silu --------------------------------
__global__ void reduce_silu_kernel(const float* __restrict__ part,
                                   const float* __restrict__ bias,
                                   float* __restrict__ out) {
    const long MN = (long)B_ * HEADH_;
    const long e = ((long)blockIdx.x * 256 + threadIdx.x) * 4;
    const int n = (int)(e % HEADH_);
    float4 a = *(const float4*)&part[e];
    #pragma unroll
    for (int z = 1; z < SPLITK; z++) {
        const float4 p = *(const float4*)&part[z * MN + e];
        a.x += p.x; a.y += p.y; a.z += p.z; a.w += p.w;
    }
    const float4 bi = *(const float4*)&bias[n];
    a.x += bi.x; a.y += bi.y; a.z += bi.z; a.w += bi.w;
    a.x = a.x / (1.f + expf(-a.x));
    a.y = a.y / (1.f + expf(-a.y));
    a.z = a.z / (1.f + expf(-a.z));
    a.w = a.w / (1.f + expf(-a.w));
    *(float4*)&out[e] = a;
}

// ---------------- fused attention per (b,h); out += attn ---------------------
__global__ __launch_bounds__(96)
void attn_kernel(const float* __restrict__ qkv, float* __restrict__ out) {
    const int h = blockIdx.x, b = blockIdx.y;
    __shared__ __align__(16) float Ks[T1_ * 32];
    __shared__ __align__(16) float Vs[T1_ * 32];
    __shared__ float S[T1_ * 67];
    const float* base = qkv + (long)b * T1_ * 768 + h * 96;

    for (int idx = threadIdx.x; idx < T1_ * 8; idx += 96) {
        int r = idx >> 3, c4 = (idx & 7) << 2;
        *(float4*)&Ks[r * 32 + c4] = *(const float4*)&base[r * 768 + 32 + c4];
        *(float4*)&Vs[r * 32 + c4] = *(const float4*)&base[r * 768 + 64 + c4];
    }
    __syncthreads();

    const int r = threadIdx.x;
    if (r < T1_) {
        float4 q4[8];
        #pragma unroll
        for (int j = 0; j < 8; j++)
            q4[j] = *(const float4*)&base[r * 768 + j * 4];

        float mx = -1e30f;
        for (int k = 0; k < T1_; k++) {
            float acc = 0.f;
            #pragma unroll
            for (int j = 0; j < 8; j++) {
                const float4 kv = *(const float4*)&Ks[k * 32 + j * 4];
                acc += q4[j].x * kv.x + q4[j].y * kv.y + q4[j].z * kv.z + q4[j].w * kv.w;
            }
            acc *= 0.17677669529663687f;
            S[r * 67 + k] = acc;
            mx = fmaxf(mx, acc);
        }
        float sum = 0.f;
        for (int k = 0; k < T1_; k++) {
            float e = expf(S[r * 67 + k] - mx);
            S[r * 67 + k] = e;
            sum += e;
        }
        const float inv = 1.f / sum;

        float4 acc4[8];
        #pragma unroll
        for (int j = 0; j < 8; j++) acc4[j] = make_float4(0.f, 0.f, 0.f, 0.f);
        for (int k = 0; k < T1_; k++) {
            const float s = S[r * 67 + k];
            #pragma unroll
            for (int j = 0; j < 8; j++) {
                const float4 vv = *(const float4*)&Vs[k * 32 + j * 4];
                acc4[j].x += s * vv.x; acc4[j].y += s * vv.y;
                acc4[j].z += s * vv.z; acc4[j].w += s * vv.w;
            }
        }
        float* op = out + ((long)b * T1_ + r) * D_ + h * HD_;
        #pragma unroll
        for (int j = 0; j < 8; j++) {
            float4 o = *(float4*)&op[j * 4];
            o.x += acc4[j].x * inv; o.y += acc4[j].y * inv;
            o.z += acc4[j].z * inv; o.w += acc4[j].w * inv;
            *(float4*)&op[j * 4] = o;
        }
    }
}

// ---------------- final classifier head --------------------------------------
__global__ void head2_kernel(const float* __restrict__ hid, const float* __restrict__ W2,
                             const float* __restrict__ b2, float* __restrict__ out) {
    int b = blockIdx.x;
    float acc[NCLS_] = {};
    for (int k = threadIdx.x; k < HEADH_; k += 256) {
        float hv = hid[(long)b * HEADH_ + k];
        #pragma unroll
        for (int c = 0; c < NCLS_; c++) acc[c] += hv * W2[k * NCLS_ + c];
    }
    __shared__ float red[256];
    for (int c = 0; c < NCLS_; c++) {
        red[threadIdx.x] = acc[c];
        __syncthreads();
        for (int o = 128; o > 0; o >>= 1) {
            if (threadIdx.x < o) red[threadIdx.x] += red[threadIdx.x + o];
            __syncthreads();
        }
        if (threadIdx.x == 0) out[b * NCLS_ + c] = red[0] + b2[c];
        __syncthreads();
    }
}

// -----------------------------------------------------------------------------
extern "C" void kernel_launch(void* const* d_in, const int* in_sizes, int n_in,
                              void* d_out, int out_size) {
    const float* x      = (const float*)d_in[0];
    const float* cls    = (const float*)d_in[1];
    const float* Wp     = (const float*)d_in[2];
    const float* bp     = (const float*)d_in[3];
    const float* qkv_w  = (const float*)d_in[4];
    const float* qkv_b  = (const float*)d_in[5];
    const float* ln_w   = (const float*)d_in[6];
    const float* ln_b   = (const float*)d_in[7];
    const float* mlp1_w = (const float*)d_in[8];
    const float* mlp1_b = (const float*)d_in[9];
    const float* mlp2_w = (const float*)d_in[10];
    const float* mlp2_b = (const float*)d_in[11];
    const float* h1w    = (const float*)d_in[12];
    const float* h1b    = (const float*)d_in[13];
    const float* h2w    = (const float*)d_in[14];
    const float* h2b    = (const float*)d_in[15];
    float* out = (float*)d_out;

    float *p_out, *p_h, *p_qkv, *p_m, *p_hid, *p_part;
    cudaGetSymbolAddress((void**)&p_out, g_out);
    cudaGetSymbolAddress((void**)&p_h,   g_h);
    cudaGetSymbolAddress((void**)&p_qkv, g_qkv);
    cudaGetSymbolAddress((void**)&p_m,   g_m);
    cudaGetSymbolAddress((void**)&p_hid, g_hid);
    cudaGetSymbolAddress((void**)&p_part, g_part);

    cudaFuncSetAttribute(gemm_tc<0,false>, cudaFuncAttributeMaxDynamicSharedMemorySize, GSMEM_TOTAL);
    cudaFuncSetAttribute(gemm_tc<1,false>, cudaFuncAttributeMaxDynamicSharedMemorySize, GSMEM_TOTAL);
    cudaFuncSetAttribute(gemm_tc<0,true>,  cudaFuncAttributeMaxDynamicSharedMemorySize, GSMEM_TOTAL);
    cudaFuncSetAttribute(gemm_tc<3,false>, cudaFuncAttributeMaxDynamicSharedMemorySize, GSMEM_TOTAL);

    dim3 gPatch(B_, T1_);
    patch_embed_kernel<<<gPatch, 256>>>(x, cls, Wp, bp, p_out);

    const int Mt = B_ * T1_;   // 16640 rows, /256 = 65 m-tiles
    for (int l = 0; l < 2; l++) {
        ln2d_kernel<<<B_, 256>>>(p_out, ln_w + l * ND_, ln_b + l * ND_, p_h);
        gemm_tc<0, false><<<dim3(768 / 128, Mt / 256), 512, GSMEM_TOTAL>>>(
            p_h, qkv_w + l * D_ * 768, qkv_b + l * 768, nullptr, p_qkv,
            Mt, 768, D_, D_);
        attn_kernel<<<dim3(H_, B_), 96>>>(p_qkv, p_out);
        ln2d_kernel<<<B_, 256>>>(p_out, ln_w + l * ND_, ln_b + l * ND_, p_h);
        gemm_tc<1, false><<<dim3(MLPH_ / 128, Mt / 256), 512, GSMEM_TOTAL>>>(
            p_h, mlp1_w + l * D_ * MLPH_, mlp1_b + l * MLPH_, nullptr, p_m,
            Mt, MLPH_, D_, D_);
        gemm_tc<0, true><<<dim3(D_ / 128, Mt / 256), 512, GSMEM_TOTAL>>>(
            p_m, mlp2_w + l * MLPH_ * D_, mlp2_b + l * D_, p_out, p_out,
            Mt, D_, MLPH_, MLPH_);
    }

    // head1 split-K: partials then fused reduce+bias+silu
    gemm_tc<3, false><<<dim3(HEADH_ / 128, B_ / 256, SPLITK), 512, GSMEM_TOTAL>>>(
        p_out, h1w, h1b, nullptr, p_part, B_, HEADH_, ND_, KCHUNK);
    reduce_silu_kernel<<<(B_ * HEADH_) / 1024, 256>>>(p_part, h1b, p_hid);

    head2_kernel<<<B_, 256>>>(p_hid, h2w, h2b, out);
}

// round 14
// speedup vs baseline: 1.3238x; 1.0786x over previous
#include <cuda_runtime.h>
#include <cuda_fp16.h>
#include <math.h>
#include <stdint.h>

#define B_    256
#define C_    3
#define IMG_  32
#define D_    256
#define H_    8
#define HD_   32
#define T1_   65
#define MLPH_ 2048
#define HEADH_ 8192
#define NCLS_ 10
#define PDIM_ 48
#define ND_   (T1_*D_)   // 16640
#define SPLITK 4
#define KCHUNK (ND_/SPLITK)   // 4160

// ---------------- scratch ----------------------------------------------------
__device__ float g_out[B_*T1_*D_];
__device__ float g_h[B_*T1_*D_];
__device__ float g_qkv[B_*T1_*3*D_];
__device__ float g_m[B_*T1_*MLPH_];
__device__ float g_hid[B_*HEADH_];
__device__ float g_part[SPLITK*B_*HEADH_];

// ---------------- patch embed + cls + positional encoding --------------------
__global__ void patch_embed_kernel(const float* __restrict__ x,
                                   const float* __restrict__ cls,
                                   const float* __restrict__ Wp,
                                   const float* __restrict__ bp,
                                   float* __restrict__ out) {
    int b = blockIdx.x;
    int t = blockIdx.y;
    int d = threadIdx.x;
    int i = d >> 1;
    float div = expf(-(float)(2 * i) * (9.210340371976184f / 256.0f));
    float ang = (float)t * div;
    float pe = (d & 1) ? cosf(ang) : sinf(ang);

    if (t == 0) {
        out[(b * T1_) * D_ + d] = cls[d] + pe;
    } else {
        __shared__ float sp[PDIM_];
        int tt = t - 1;
        int ni = tt >> 3, nj = tt & 7;
        if (d < PDIM_) {
            int c  = d / 16;
            int pi = (d >> 2) & 3;
            int pj = d & 3;
            sp[d] = x[((b * C_ + c) * IMG_ + ni * 4 + pi) * IMG_ + nj * 4 + pj];
        }
        __syncthreads();
        float acc = bp[d];
        #pragma unroll
        for (int k = 0; k < PDIM_; k++) acc += sp[k] * Wp[k * D_ + d];
        out[((b * T1_) + t) * D_ + d] = acc + pe;
    }
}

// ---------------- LayerNorm over whole (T1,D) slab per sample ----------------
__global__ void ln2d_kernel(const float* __restrict__ X,
                            const float* __restrict__ w,
                            const float* __restrict__ bb,
                            float* __restrict__ Y) {
    int b = blockIdx.x;
    const float* xb = X + b * ND_;
    float s = 0.f, s2 = 0.f;
    for (int i = threadIdx.x; i < ND_; i += 256) {
        float v = xb[i];
        s += v; s2 += v * v;
    }
    __shared__ float rs[8], rs2[8], bc[2];
    #pragma unroll
    for (int o = 16; o > 0; o >>= 1) {
        s  += __shfl_down_sync(0xffffffffu, s,  o);
        s2 += __shfl_down_sync(0xffffffffu, s2, o);
    }
    int wid = threadIdx.x >> 5, lid = threadIdx.x & 31;
    if (lid == 0) { rs[wid] = s; rs2[wid] = s2; }
    __syncthreads();
    if (threadIdx.x == 0) {
        float ts = 0.f, ts2 = 0.f;
        #pragma unroll
        for (int k = 0; k < 8; k++) { ts += rs[k]; ts2 += rs2[k]; }
        float mu  = ts / (float)ND_;
        float var = ts2 / (float)ND_ - mu * mu;
        bc[0] = mu;
        bc[1] = rsqrtf(var + 1e-5f);
    }
    __syncthreads();
    float mu = bc[0], rsg = bc[1];
    float* yb = Y + b * ND_;
    for (int i = threadIdx.x; i < ND_; i += 256) {
        yb[i] = (xb[i] - mu) * rsg * w[i] + bb[i];
    }
}

// ---------------- fp16 tensor-core GEMM, BK=64 --------------------------------
// C(M,N) = act(A(M,K) @ W(K,N) + bias) (+R).
// A -> fp16 hi only; W -> fp16 hi (+ lo if WLO). fp32 accumulate.
// CTA tile 256x128, BK=64, 512 threads (16 warps), warp tile 64x32.
// ACT: 0 none, 1 relu, 2 silu, 3 raw partial (split-K, z-offset output)
#define PITCH 72                      // fp16 elements per smem row (64 + 8 pad)
#define SA_H 0                        // 256*72*2 = 36864
#define SB_H 36864                    // 128*72*2 = 18432
#define SB_L 55296
#define BUFSZ 73728
#define GSMEM_TOTAL (2*BUFSZ)         // 147456

__device__ __forceinline__ void mma16816h(float* c, const uint32_t* a, const uint32_t* b) {
    asm volatile(
        "mma.sync.aligned.m16n8k16.row.col.f32.f16.f16.f32 "
        "{%0,%1,%2,%3}, {%4,%5,%6,%7}, {%8,%9}, {%0,%1,%2,%3};"
        : "+f"(c[0]), "+f"(c[1]), "+f"(c[2]), "+f"(c[3])
        : "r"(a[0]), "r"(a[1]), "r"(a[2]), "r"(a[3]), "r"(b[0]), "r"(b[1]));
}
__device__ __forceinline__ void split_pair_h(float x, float y, __half2& hi, __half2& lo) {
    hi = __floats2half2_rn(x, y);
    float2 hf = __half22float2(hi);
    lo = __floats2half2_rn(x - hf.x, y - hf.y);
}

template<int ACT, bool RES, bool WLO>
__global__ void __launch_bounds__(512, 1) gemm_tc(
    const float* __restrict__ A, const float* __restrict__ W,
    const float* __restrict__ bias, const float* __restrict__ R,
    float* __restrict__ Cc, int M, int N, int K, int kChunk)
{
    extern __shared__ char smem[];
    const int tid = threadIdx.x;
    const int wid = tid >> 5;
    const int lane = tid & 31;
    const int wm = wid >> 2, wn = wid & 3;       // 4x4 warps -> 64x32 tiles
    const int m0 = blockIdx.y * 256, n0 = blockIdx.x * 128;
    const int kbase = blockIdx.z * kChunk;
    float* Cz = Cc + (long)blockIdx.z * M * N;
    const int gid = lane >> 2, tig = lane & 3;

    const int bn = tid & 127;                    // W fill: n index
    const int bkh = (tid >> 7) * 16;             // W fill: k group of 16

    float c[4][4][4];
    #pragma unroll
    for (int i = 0; i < 4; i++)
        #pragma unroll
        for (int j = 0; j < 4; j++)
            #pragma unroll
            for (int r = 0; r < 4; r++) c[i][j][r] = 0.f;

    const int nk = kChunk / 64;
    uint32_t rah[16];                 // A hi: 8 float4 -> 16 half2
    uint32_t rwh[8], rwl[8];          // W hi/lo: 16 floats -> 8+8 half2

    auto ldg_tile = [&](int t) {
        #pragma unroll
        for (int i = 0; i < 8; i++) {
            int lin = tid + i * 512;
            int row = lin >> 4, q = lin & 15;
            float4 v = *(const float4*)&A[(long)(m0 + row) * K + kbase + t * 64 + q * 4];
            __half2 h0 = __floats2half2_rn(v.x, v.y);
            __half2 h1 = __floats2half2_rn(v.z, v.w);
            rah[2 * i]     = *(uint32_t*)&h0;
            rah[2 * i + 1] = *(uint32_t*)&h1;
        }
        const float* Wb = W + (long)(kbase + t * 64 + bkh) * N + n0 + bn;
        #pragma unroll
        for (int p = 0; p < 8; p++) {
            float w0 = Wb[(long)(2 * p) * N];
            float w1 = Wb[(long)(2 * p + 1) * N];
            if (WLO) {
                __half2 h, l;
                split_pair_h(w0, w1, h, l);
                rwh[p] = *(uint32_t*)&h;
                rwl[p] = *(uint32_t*)&l;
            } else {
                __half2 h = __floats2half2_rn(w0, w1);
                rwh[p] = *(uint32_t*)&h;
            }
        }
    };
    auto sts_tile = [&](int buf) {
        char* base = smem + buf * BUFSZ;
        #pragma unroll
        for (int i = 0; i < 8; i++) {
            int lin = tid + i * 512;
            int row = lin >> 4, q = lin & 15;
            int e = row * PITCH + q * 4;
            *(uint2*)(base + SA_H + e * 2) = make_uint2(rah[2 * i], rah[2 * i + 1]);
        }
        #pragma unroll
        for (int p = 0; p < 8; p++) {
            int e = bn * PITCH + bkh + 2 * p;
            *(uint32_t*)(base + SB_H + e * 2) = rwh[p];
            if (WLO) *(uint32_t*)(base + SB_L + e * 2) = rwl[p];
        }
    };

    ldg_tile(0);
    sts_tile(0);
    __syncthreads();

    for (int t = 0; t < nk; t++) {
        const int buf = t & 1;
        if (t + 1 < nk) ldg_tile(t + 1);

        const char* ahp = smem + buf * BUFSZ + SA_H;
        const char* bhp = smem + buf * BUFSZ + SB_H;
        const char* blp = smem + buf * BUFSZ + SB_L;

        #pragma unroll
        for (int ks = 0; ks < 4; ks++) {
            const int acol = ks * 16 + tig * 2;
            uint32_t bh[4][2], bl[4][2];
            #pragma unroll
            for (int an = 0; an < 4; an++) {
                const int brow = wn * 32 + an * 8 + gid;
                const int e = (brow * PITCH + acol) * 2;
                bh[an][0] = *(const uint32_t*)(bhp + e);
                bh[an][1] = *(const uint32_t*)(bhp + e + 16);
                if (WLO) {
                    bl[an][0] = *(const uint32_t*)(blp + e);
                    bl[an][1] = *(const uint32_t*)(blp + e + 16);
                }
            }
            #pragma unroll
            for (int am = 0; am < 4; am++) {
                const int arow = wm * 64 + am * 16 + gid;
                const int e00 = (arow * PITCH + acol) * 2;
                const int e10 = ((arow + 8) * PITCH + acol) * 2;
                uint32_t ah[4];
                ah[0] = *(const uint32_t*)(ahp + e00);
                ah[1] = *(const uint32_t*)(ahp + e10);
                ah[2] = *(const uint32_t*)(ahp + e00 + 16);
                ah[3] = *(const uint32_t*)(ahp + e10 + 16);
                #pragma unroll
                for (int an = 0; an < 4; an++) {
                    mma16816h(c[am][an], ah, bh[an]);
                    if (WLO) mma16816h(c[am][an], ah, bl[an]);
                }
            }
        }

        if (t + 1 < nk) sts_tile(buf ^ 1);
        __syncthreads();
    }

    // ---- epilogue ----
    #pragma unroll
    for (int am = 0; am < 4; am++) {
        #pragma unroll
        for (int an = 0; an < 4; an++) {
            const int col = n0 + wn * 32 + an * 8 + tig * 2;
            float bx = 0.f, by = 0.f;
            if (ACT != 3) { bx = bias[col]; by = bias[col + 1]; }
            #pragma unroll
            for (int hrow = 0; hrow < 2; hrow++) {
                const int m = m0 + wm * 64 + am * 16 + gid + hrow * 8;
                float vx = c[am][an][hrow * 2 + 0] + bx;
                float vy = c[am][an][hrow * 2 + 1] + by;
                if (ACT == 1) { vx = fmaxf(vx, 0.f); vy = fmaxf(vy, 0.f); }
                if (ACT == 2) {
                    vx = vx / (1.f + expf(-vx));
                    vy = vy / (1.f + expf(-vy));
                }
                if (RES) {
                    const float2 r2 = *(const float2*)&R[(long)m * N + col];
                    vx += r2.x; vy += r2.y;
                }
                *(float2*)&Cz[(long)m * N + col] = make_float2(vx, vy);
            }
        }
    }
}

// ---------------- split-K reduce + bias + silu --------------------------------
__global__ void reduce_silu_kernel(const float* __restrict__ part,
                                   const float* __restrict__ bias,
                                   float* __restrict__ out) {
    const long MN = (long)B_ * HEADH_;
    const long e = ((long)blockIdx.x * 256 + threadIdx.x) * 4;
    const int n = (int)(e % HEADH_);
    float4 a = *(const float4*)&part[e];
    #pragma unroll
    for (int z = 1; z < SPLITK; z++) {
        const float4 p = *(const float4*)&part[z * MN + e];
        a.x += p.x; a.y += p.y; a.z += p.z; a.w += p.w;
    }
    const float4 bi = *(const float4*)&bias[n];
    a.x += bi.x; a.y += bi.y; a.z += bi.z; a.w += bi.w;
    a.x = a.x / (1.f + expf(-a.x));
    a.y = a.y / (1.f + expf(-a.y));
    a.z = a.z / (1.f + expf(-a.z));
    a.w = a.w / (1.f + expf(-a.w));
    *(float4*)&out[e] = a;
}

// ---------------- fused attention per (b,h); out += attn ---------------------
__global__ __launch_bounds__(96)
void attn_kernel(const float* __restrict__ qkv, float* __restrict__ out) {
    const int h = blockIdx.x, b = blockIdx.y;
    __shared__ __align__(16) float Ks[T1_ * 32];
    __shared__ __align__(16) float Vs[T1_ * 32];
    __shared__ float S[T1_ * 67];
    const float* base = qkv + (long)b * T1_ * 768 + h * 96;

    for (int idx = threadIdx.x; idx < T1_ * 8; idx += 96) {
        int r = idx >> 3, c4 = (idx & 7) << 2;
        *(float4*)&Ks[r * 32 + c4] = *(const float4*)&base[r * 768 + 32 + c4];
        *(float4*)&Vs[r * 32 + c4] = *(const float4*)&base[r * 768 + 64 + c4];
    }
    __syncthreads();

    const int r = threadIdx.x;
    if (r < T1_) {
        float4 q4[8];
        #pragma unroll
        for (int j = 0; j < 8; j++)
            q4[j] = *(const float4*)&base[r * 768 + j * 4];

        float mx = -1e30f;
        for (int k = 0; k < T1_; k++) {
            float acc = 0.f;
            #pragma unroll
            for (int j = 0; j < 8; j++) {
                const float4 kv = *(const float4*)&Ks[k * 32 + j * 4];
                acc += q4[j].x * kv.x + q4[j].y * kv.y + q4[j].z * kv.z + q4[j].w * kv.w;
            }
            acc *= 0.17677669529663687f;
            S[r * 67 + k] = acc;
            mx = fmaxf(mx, acc);
        }
        float sum = 0.f;
        for (int k = 0; k < T1_; k++) {
            float e = expf(S[r * 67 + k] - mx);
            S[r * 67 + k] = e;
            sum += e;
        }
        const float inv = 1.f / sum;

        float4 acc4[8];
        #pragma unroll
        for (int j = 0; j < 8; j++) acc4[j] = make_float4(0.f, 0.f, 0.f, 0.f);
        for (int k = 0; k < T1_; k++) {
            const float s = S[r * 67 + k];
            #pragma unroll
            for (int j = 0; j < 8; j++) {
                const float4 vv = *(const float4*)&Vs[k * 32 + j * 4];
                acc4[j].x += s * vv.x; acc4[j].y += s * vv.y;
                acc4[j].z += s * vv.z; acc4[j].w += s * vv.w;
            }
        }
        float* op = out + ((long)b * T1_ + r) * D_ + h * HD_;
        #pragma unroll
        for (int j = 0; j < 8; j++) {
            float4 o = *(float4*)&op[j * 4];
            o.x += acc4[j].x * inv; o.y += acc4[j].y * inv;
            o.z += acc4[j].z * inv; o.w += acc4[j].w * inv;
            *(float4*)&op[j * 4] = o;
        }
    }
}

// ---------------- final classifier head --------------------------------------
__global__ void head2_kernel(const float* __restrict__ hid, const float* __restrict__ W2,
                             const float* __restrict__ b2, float* __restrict__ out) {
    int b = blockIdx.x;
    float acc[NCLS_] = {};
    for (int k = threadIdx.x; k < HEADH_; k += 256) {
        float hv = hid[(long)b * HEADH_ + k];
        #pragma unroll
        for (int c = 0; c < NCLS_; c++) acc[c] += hv * W2[k * NCLS_ + c];
    }
    __shared__ float red[256];
    for (int c = 0; c < NCLS_; c++) {
        red[threadIdx.x] = acc[c];
        __syncthreads();
        for (int o = 128; o > 0; o >>= 1) {
            if (threadIdx.x < o) red[threadIdx.x] += red[threadIdx.x + o];
            __syncthreads();
        }
        if (threadIdx.x == 0) out[b * NCLS_ + c] = red[0] + b2[c];
        __syncthreads();
    }
}

// -----------------------------------------------------------------------------
extern "C" void kernel_launch(void* const* d_in, const int* in_sizes, int n_in,
                              void* d_out, int out_size) {
    const float* x      = (const float*)d_in[0];
    const float* cls    = (const float*)d_in[1];
    const float* Wp     = (const float*)d_in[2];
    const float* bp     = (const float*)d_in[3];
    const float* qkv_w  = (const float*)d_in[4];
    const float* qkv_b  = (const float*)d_in[5];
    const float* ln_w   = (const float*)d_in[6];
    const float* ln_b   = (const float*)d_in[7];
    const float* mlp1_w = (const float*)d_in[8];
    const float* mlp1_b = (const float*)d_in[9];
    const float* mlp2_w = (const float*)d_in[10];
    const float* mlp2_b = (const float*)d_in[11];
    const float* h1w    = (const float*)d_in[12];
    const float* h1b    = (const float*)d_in[13];
    const float* h2w    = (const float*)d_in[14];
    const float* h2b    = (const float*)d_in[15];
    float* out = (float*)d_out;

    float *p_out, *p_h, *p_qkv, *p_m, *p_hid, *p_part;
    cudaGetSymbolAddress((void**)&p_out, g_out);
    cudaGetSymbolAddress((void**)&p_h,   g_h);
    cudaGetSymbolAddress((void**)&p_qkv, g_qkv);
    cudaGetSymbolAddress((void**)&p_m,   g_m);
    cudaGetSymbolAddress((void**)&p_hid, g_hid);
    cudaGetSymbolAddress((void**)&p_part, g_part);

    cudaFuncSetAttribute((const void*)gemm_tc<0,false,true>, cudaFuncAttributeMaxDynamicSharedMemorySize, GSMEM_TOTAL);
    cudaFuncSetAttribute((const void*)gemm_tc<1,false,true>, cudaFuncAttributeMaxDynamicSharedMemorySize, GSMEM_TOTAL);
    cudaFuncSetAttribute((const void*)gemm_tc<0,true,true>,  cudaFuncAttributeMaxDynamicSharedMemorySize, GSMEM_TOTAL);
    cudaFuncSetAttribute((const void*)gemm_tc<3,false,false>, cudaFuncAttributeMaxDynamicSharedMemorySize, GSMEM_TOTAL);

    dim3 gPatch(B_, T1_);
    patch_embed_kernel<<<gPatch, 256>>>(x, cls, Wp, bp, p_out);

    const int Mt = B_ * T1_;   // 16640 rows, /256 = 65 m-tiles
    for (int l = 0; l < 2; l++) {
        ln2d_kernel<<<B_, 256>>>(p_out, ln_w + l * ND_, ln_b + l * ND_, p_h);
        gemm_tc<0, false, true><<<dim3(768 / 128, Mt / 256), 512, GSMEM_TOTAL>>>(
            p_h, qkv_w + l * D_ * 768, qkv_b + l * 768, nullptr, p_qkv,
            Mt, 768, D_, D_);
        attn_kernel<<<dim3(H_, B_), 96>>>(p_qkv, p_out);
        ln2d_kernel<<<B_, 256>>>(p_out, ln_w + l * ND_, ln_b + l * ND_, p_h);
        gemm_tc<1, false, true><<<dim3(MLPH_ / 128, Mt / 256), 512, GSMEM_TOTAL>>>(
            p_h, mlp1_w + l * D_ * MLPH_, mlp1_b + l * MLPH_, nullptr, p_m,
            Mt, MLPH_, D_, D_);
        gemm_tc<0, true, true><<<dim3(D_ / 128, Mt / 256), 512, GSMEM_TOTAL>>>(
            p_m, mlp2_w + l * MLPH_ * D_, mlp2_b + l * D_, p_out, p_out,
            Mt, D_, MLPH_, MLPH_);
    }

    // head1 split-K (1-term fp16 W): partials then fused reduce+bias+silu
    gemm_tc<3, false, false><<<dim3(HEADH_ / 128, B_ / 256, SPLITK), 512, GSMEM_TOTAL>>>(
        p_out, h1w, h1b, nullptr, p_part, B_, HEADH_, ND_, KCHUNK);
    reduce_silu_kernel<<<(B_ * HEADH_) / 1024, 256>>>(p_part, h1b, p_hid);

    head2_kernel<<<B_, 256>>>(p_hid, h2w, h2b, out);
}

// round 15
// speedup vs baseline: 1.3626x; 1.0293x over previous
#include <cuda_runtime.h>
#include <cuda_fp16.h>
#include <math.h>
#include <stdint.h>

#define B_    256
#define C_    3
#define IMG_  32
#define D_    256
#define H_    8
#define HD_   32
#define T1_   65
#define MLPH_ 2048
#define HEADH_ 8192
#define NCLS_ 10
#define PDIM_ 48
#define ND_   (T1_*D_)   // 16640
#define SPLITK 4
#define KCHUNK (ND_/SPLITK)   // 4160

// ---------------- scratch ----------------------------------------------------
__device__ float g_out[B_*T1_*D_];
__device__ float g_h[B_*T1_*D_];
__device__ float g_qkv[B_*T1_*3*D_];
__device__ float g_m[B_*T1_*MLPH_];
__device__ float g_hid[B_*HEADH_];
__device__ float g_part[SPLITK*B_*HEADH_];

// ---------------- patch embed + cls + positional encoding --------------------
__global__ void patch_embed_kernel(const float* __restrict__ x,
                                   const float* __restrict__ cls,
                                   const float* __restrict__ Wp,
                                   const float* __restrict__ bp,
                                   float* __restrict__ out) {
    int b = blockIdx.x;
    int t = blockIdx.y;
    int d = threadIdx.x;
    int i = d >> 1;
    float div = expf(-(float)(2 * i) * (9.210340371976184f / 256.0f));
    float ang = (float)t * div;
    float pe = (d & 1) ? cosf(ang) : sinf(ang);

    if (t == 0) {
        out[(b * T1_) * D_ + d] = cls[d] + pe;
    } else {
        __shared__ float sp[PDIM_];
        int tt = t - 1;
        int ni = tt >> 3, nj = tt & 7;
        if (d < PDIM_) {
            int c  = d / 16;
            int pi = (d >> 2) & 3;
            int pj = d & 3;
            sp[d] = x[((b * C_ + c) * IMG_ + ni * 4 + pi) * IMG_ + nj * 4 + pj];
        }
        __syncthreads();
        float acc = bp[d];
        #pragma unroll
        for (int k = 0; k < PDIM_; k++) acc += sp[k] * Wp[k * D_ + d];
        out[((b * T1_) + t) * D_ + d] = acc + pe;
    }
}

// ---------------- LayerNorm over whole (T1,D) slab per sample ----------------
__global__ void ln2d_kernel(const float* __restrict__ X,
                            const float* __restrict__ w,
                            const float* __restrict__ bb,
                            float* __restrict__ Y) {
    int b = blockIdx.x;
    const float* xb = X + b * ND_;
    float s = 0.f, s2 = 0.f;
    for (int i = threadIdx.x; i < ND_; i += 256) {
        float v = xb[i];
        s += v; s2 += v * v;
    }
    __shared__ float rs[8], rs2[8], bc[2];
    #pragma unroll
    for (int o = 16; o > 0; o >>= 1) {
        s  += __shfl_down_sync(0xffffffffu, s,  o);
        s2 += __shfl_down_sync(0xffffffffu, s2, o);
    }
    int wid = threadIdx.x >> 5, lid = threadIdx.x & 31;
    if (lid == 0) { rs[wid] = s; rs2[wid] = s2; }
    __syncthreads();
    if (threadIdx.x == 0) {
        float ts = 0.f, ts2 = 0.f;
        #pragma unroll
        for (int k = 0; k < 8; k++) { ts += rs[k]; ts2 += rs2[k]; }
        float mu  = ts / (float)ND_;
        float var = ts2 / (float)ND_ - mu * mu;
        bc[0] = mu;
        bc[1] = rsqrtf(var + 1e-5f);
    }
    __syncthreads();
    float mu = bc[0], rsg = bc[1];
    float* yb = Y + b * ND_;
    for (int i = threadIdx.x; i < ND_; i += 256) {
        yb[i] = (xb[i] - mu) * rsg * w[i] + bb[i];
    }
}

// ---------------- fp16 tensor-core GEMM, BK=64, 3-stage pipeline --------------
// C(M,N) = act(A(M,K) @ W(K,N) + bias) (+R).
// A -> fp16 hi only; W -> fp16 hi (+ lo if WLO). fp32 accumulate.
// CTA tile 256x128, BK=64, 512 threads (16 warps), warp tile 64x32.
// ACT: 0 none, 1 relu, 2 silu, 3 raw partial (split-K, z-offset output)
#define PITCH 72                      // fp16 elements per smem row (64 + 8 pad)
#define SA_H 0                        // 256*72*2 = 36864
#define SB_H 36864                    // 128*72*2 = 18432
#define SB_L 55296
#define BUFSZ 73728
#define GSMEM_TOTAL (3*BUFSZ)         // 221184 (3-stage)

__device__ __forceinline__ void mma16816h(float* c, const uint32_t* a, const uint32_t* b) {
    asm volatile(
        "mma.sync.aligned.m16n8k16.row.col.f32.f16.f16.f32 "
        "{%0,%1,%2,%3}, {%4,%5,%6,%7}, {%8,%9}, {%0,%1,%2,%3};"
        : "+f"(c[0]), "+f"(c[1]), "+f"(c[2]), "+f"(c[3])
        : "r"(a[0]), "r"(a[1]), "r"(a[2]), "r"(a[3]), "r"(b[0]), "r"(b[1]));
}
__device__ __forceinline__ void split_pair_h(float x, float y, __half2& hi, __half2& lo) {
    hi = __floats2half2_rn(x, y);
    float2 hf = __half22float2(hi);
    lo = __floats2half2_rn(x - hf.x, y - hf.y);
}

template<int ACT, bool RES, bool WLO>
__global__ void __launch_bounds__(512, 1) gemm_tc(
    const float* __restrict__ A, const float* __restrict__ W,
    const float* __restrict__ bias, const float* __restrict__ R,
    float* __restrict__ Cc, int M, int N, int K, int kChunk)
{
    extern __shared__ char smem[];
    const int tid = threadIdx.x;
    const int wid = tid >> 5;
    const int lane = tid & 31;
    const int wm = wid >> 2, wn = wid & 3;       // 4x4 warps -> 64x32 tiles
    const int m0 = blockIdx.y * 256, n0 = blockIdx.x * 128;
    const int kbase = blockIdx.z * kChunk;
    float* Cz = Cc + (long)blockIdx.z * M * N;
    const int gid = lane >> 2, tig = lane & 3;

    const int bn = tid & 127;                    // W fill: n index
    const int bkh = (tid >> 7) * 16;             // W fill: k group of 16

    float c[4][4][4];
    #pragma unroll
    for (int i = 0; i < 4; i++)
        #pragma unroll
        for (int j = 0; j < 4; j++)
            #pragma unroll
            for (int r = 0; r < 4; r++) c[i][j][r] = 0.f;

    const int nk = kChunk / 64;
    uint32_t rah[16];                 // A hi: 8 float4 -> 16 half2
    uint32_t rwh[8], rwl[8];          // W hi/lo

    auto ldg_tile = [&](int t) {
        #pragma unroll
        for (int i = 0; i < 8; i++) {
            int lin = tid + i * 512;
            int row = lin >> 4, q = lin & 15;
            float4 v = *(const float4*)&A[(long)(m0 + row) * K + kbase + t * 64 + q * 4];
            __half2 h0 = __floats2half2_rn(v.x, v.y);
            __half2 h1 = __floats2half2_rn(v.z, v.w);
            rah[2 * i]     = *(uint32_t*)&h0;
            rah[2 * i + 1] = *(uint32_t*)&h1;
        }
        const float* Wb = W + (long)(kbase + t * 64 + bkh) * N + n0 + bn;
        #pragma unroll
        for (int p = 0; p < 8; p++) {
            float w0 = Wb[(long)(2 * p) * N];
            float w1 = Wb[(long)(2 * p + 1) * N];
            if (WLO) {
                __half2 h, l;
                split_pair_h(w0, w1, h, l);
                rwh[p] = *(uint32_t*)&h;
                rwl[p] = *(uint32_t*)&l;
            } else {
                __half2 h = __floats2half2_rn(w0, w1);
                rwh[p] = *(uint32_t*)&h;
            }
        }
    };
    auto sts_tile = [&](int buf) {
        char* base = smem + buf * BUFSZ;
        #pragma unroll
        for (int i = 0; i < 8; i++) {
            int lin = tid + i * 512;
            int row = lin >> 4, q = lin & 15;
            int e = row * PITCH + q * 4;
            *(uint2*)(base + SA_H + e * 2) = make_uint2(rah[2 * i], rah[2 * i + 1]);
        }
        #pragma unroll
        for (int p = 0; p < 8; p++) {
            int e = bn * PITCH + bkh + 2 * p;
            *(uint32_t*)(base + SB_H + e * 2) = rwh[p];
            if (WLO) *(uint32_t*)(base + SB_L + e * 2) = rwl[p];
        }
    };

    // 3-stage prologue: tile0 in smem, tile1 in regs
    ldg_tile(0);
    sts_tile(0);
    if (nk > 1) ldg_tile(1);
    __syncthreads();

    for (int t = 0; t < nk; t++) {
        const int buf = t % 3;
        // store tile t+1 (regs from previous iteration / prologue)
        if (t + 1 < nk) sts_tile((t + 1) % 3);
        // issue loads for tile t+2 (has ~2 iterations to complete)
        if (t + 2 < nk) ldg_tile(t + 2);

        const char* ahp = smem + buf * BUFSZ + SA_H;
        const char* bhp = smem + buf * BUFSZ + SB_H;
        const char* blp = smem + buf * BUFSZ + SB_L;

        #pragma unroll
        for (int ks = 0; ks < 4; ks++) {
            const int acol = ks * 16 + tig * 2;
            uint32_t bh[4][2], bl[4][2];
            #pragma unroll
            for (int an = 0; an < 4; an++) {
                const int brow = wn * 32 + an * 8 + gid;
                const int e = (brow * PITCH + acol) * 2;
                bh[an][0] = *(const uint32_t*)(bhp + e);
                bh[an][1] = *(const uint32_t*)(bhp + e + 16);
                if (WLO) {
                    bl[an][0] = *(const uint32_t*)(blp + e);
                    bl[an][1] = *(const uint32_t*)(blp + e + 16);
                }
            }
            #pragma unroll
            for (int am = 0; am < 4; am++) {
                const int arow = wm * 64 + am * 16 + gid;
                const int e00 = (arow * PITCH + acol) * 2;
                const int e10 = ((arow + 8) * PITCH + acol) * 2;
                uint32_t ah[4];
                ah[0] = *(const uint32_t*)(ahp + e00);
                ah[1] = *(const uint32_t*)(ahp + e10);
                ah[2] = *(const uint32_t*)(ahp + e00 + 16);
                ah[3] = *(const uint32_t*)(ahp + e10 + 16);
                #pragma unroll
                for (int an = 0; an < 4; an++) {
                    mma16816h(c[am][an], ah, bh[an]);
                    if (WLO) mma16816h(c[am][an], ah, bl[an]);
                }
            }
        }
        __syncthreads();
    }

    // ---- epilogue ----
    #pragma unroll
    for (int am = 0; am < 4; am++) {
        #pragma unroll
        for (int an = 0; an < 4; an++) {
            const int col = n0 + wn * 32 + an * 8 + tig * 2;
            float bx = 0.f, by = 0.f;
            if (ACT != 3) { bx = bias[col]; by = bias[col + 1]; }
            #pragma unroll
            for (int hrow = 0; hrow < 2; hrow++) {
                const int m = m0 + wm * 64 + am * 16 + gid + hrow * 8;
                float vx = c[am][an][hrow * 2 + 0] + bx;
                float vy = c[am][an][hrow * 2 + 1] + by;
                if (ACT == 1) { vx = fmaxf(vx, 0.f); vy = fmaxf(vy, 0.f); }
                if (ACT == 2) {
                    vx = vx / (1.f + expf(-vx));
                    vy = vy / (1.f + expf(-vy));
                }
                if (RES) {
                    const float2 r2 = *(const float2*)&R[(long)m * N + col];
                    vx += r2.x; vy += r2.y;
                }
                *(float2*)&Cz[(long)m * N + col] = make_float2(vx, vy);
            }
        }
    }
}

// ---------------- split-K reduce + bias + silu --------------------------------
__global__ void reduce_silu_kernel(const float* __restrict__ part,
                                   const float* __restrict__ bias,
                                   float* __restrict__ out) {
    const long MN = (long)B_ * HEADH_;
    const long e = ((long)blockIdx.x * 256 + threadIdx.x) * 4;
    const int n = (int)(e % HEADH_);
    float4 a = *(const float4*)&part[e];
    #pragma unroll
    for (int z = 1; z < SPLITK; z++) {
        const float4 p = *(const float4*)&part[z * MN + e];
        a.x += p.x; a.y += p.y; a.z += p.z; a.w += p.w;
    }
    const float4 bi = *(const float4*)&bias[n];
    a.x += bi.x; a.y += bi.y; a.z += bi.z; a.w += bi.w;
    a.x = a.x / (1.f + expf(-a.x));
    a.y = a.y / (1.f + expf(-a.y));
    a.z = a.z / (1.f + expf(-a.z));
    a.w = a.w / (1.f + expf(-a.w));
    *(float4*)&out[e] = a;
}

// ---------------- fused attention per (b,h); out += attn ---------------------
__global__ __launch_bounds__(96)
void attn_kernel(const float* __restrict__ qkv, float* __restrict__ out) {
    const int h = blockIdx.x, b = blockIdx.y;
    __shared__ __align__(16) float Ks[T1_ * 32];
    __shared__ __align__(16) float Vs[T1_ * 32];
    __shared__ float S[T1_ * 67];
    const float* base = qkv + (long)b * T1_ * 768 + h * 96;

    for (int idx = threadIdx.x; idx < T1_ * 8; idx += 96) {
        int r = idx >> 3, c4 = (idx & 7) << 2;
        *(float4*)&Ks[r * 32 + c4] = *(const float4*)&base[r * 768 + 32 + c4];
        *(float4*)&Vs[r * 32 + c4] = *(const float4*)&base[r * 768 + 64 + c4];
    }
    __syncthreads();

    const int r = threadIdx.x;
    if (r < T1_) {
        float4 q4[8];
        #pragma unroll
        for (int j = 0; j < 8; j++)
            q4[j] = *(const float4*)&base[r * 768 + j * 4];

        float mx = -1e30f;
        for (int k = 0; k < T1_; k++) {
            float acc = 0.f;
            #pragma unroll
            for (int j = 0; j < 8; j++) {
                const float4 kv = *(const float4*)&Ks[k * 32 + j * 4];
                acc += q4[j].x * kv.x + q4[j].y * kv.y + q4[j].z * kv.z + q4[j].w * kv.w;
            }
            acc *= 0.17677669529663687f;
            S[r * 67 + k] = acc;
            mx = fmaxf(mx, acc);
        }
        float sum = 0.f;
        for (int k = 0; k < T1_; k++) {
            float e = expf(S[r * 67 + k] - mx);
            S[r * 67 + k] = e;
            sum += e;
        }
        const float inv = 1.f / sum;

        float4 acc4[8];
        #pragma unroll
        for (int j = 0; j < 8; j++) acc4[j] = make_float4(0.f, 0.f, 0.f, 0.f);
        for (int k = 0; k < T1_; k++) {
            const float s = S[r * 67 + k];
            #pragma unroll
            for (int j = 0; j < 8; j++) {
                const float4 vv = *(const float4*)&Vs[k * 32 + j * 4];
                acc4[j].x += s * vv.x; acc4[j].y += s * vv.y;
                acc4[j].z += s * vv.z; acc4[j].w += s * vv.w;
            }
        }
        float* op = out + ((long)b * T1_ + r) * D_ + h * HD_;
        #pragma unroll
        for (int j = 0; j < 8; j++) {
            float4 o = *(float4*)&op[j * 4];
            o.x += acc4[j].x * inv; o.y += acc4[j].y * inv;
            o.z += acc4[j].z * inv; o.w += acc4[j].w * inv;
            *(float4*)&op[j * 4] = o;
        }
    }
}

// ---------------- final classifier head --------------------------------------
__global__ void head2_kernel(const float* __restrict__ hid, const float* __restrict__ W2,
                             const float* __restrict__ b2, float* __restrict__ out) {
    int b = blockIdx.x;
    float acc[NCLS_] = {};
    for (int k = threadIdx.x; k < HEADH_; k += 256) {
        float hv = hid[(long)b * HEADH_ + k];
        #pragma unroll
        for (int c = 0; c < NCLS_; c++) acc[c] += hv * W2[k * NCLS_ + c];
    }
    __shared__ float red[256];
    for (int c = 0; c < NCLS_; c++) {
        red[threadIdx.x] = acc[c];
        __syncthreads();
        for (int o = 128; o > 0; o >>= 1) {
            if (threadIdx.x < o) red[threadIdx.x] += red[threadIdx.x + o];
            __syncthreads();
        }
        if (threadIdx.x == 0) out[b * NCLS_ + c] = red[0] + b2[c];
        __syncthreads();
    }
}

// -----------------------------------------------------------------------------
extern "C" void kernel_launch(void* const* d_in, const int* in_sizes, int n_in,
                              void* d_out, int out_size) {
    const float* x      = (const float*)d_in[0];
    const float* cls    = (const float*)d_in[1];
    const float* Wp     = (const float*)d_in[2];
    const float* bp     = (const float*)d_in[3];
    const float* qkv_w  = (const float*)d_in[4];
    const float* qkv_b  = (const float*)d_in[5];
    const float* ln_w   = (const float*)d_in[6];
    const float* ln_b   = (const float*)d_in[7];
    const float* mlp1_w = (const float*)d_in[8];
    const float* mlp1_b = (const float*)d_in[9];
    const float* mlp2_w = (const float*)d_in[10];
    const float* mlp2_b = (const float*)d_in[11];
    const float* h1w    = (const float*)d_in[12];
    const float* h1b    = (const float*)d_in[13];
    const float* h2w    = (const float*)d_in[14];
    const float* h2b    = (const float*)d_in[15];
    float* out = (float*)d_out;

    float *p_out, *p_h, *p_qkv, *p_m, *p_hid, *p_part;
    cudaGetSymbolAddress((void**)&p_out, g_out);
    cudaGetSymbolAddress((void**)&p_h,   g_h);
    cudaGetSymbolAddress((void**)&p_qkv, g_qkv);
    cudaGetSymbolAddress((void**)&p_m,   g_m);
    cudaGetSymbolAddress((void**)&p_hid, g_hid);
    cudaGetSymbolAddress((void**)&p_part, g_part);

    cudaFuncSetAttribute((const void*)gemm_tc<0,false,true>,  cudaFuncAttributeMaxDynamicSharedMemorySize, GSMEM_TOTAL);
    cudaFuncSetAttribute((const void*)gemm_tc<1,false,true>,  cudaFuncAttributeMaxDynamicSharedMemorySize, GSMEM_TOTAL);
    cudaFuncSetAttribute((const void*)gemm_tc<0,true,true>,   cudaFuncAttributeMaxDynamicSharedMemorySize, GSMEM_TOTAL);
    cudaFuncSetAttribute((const void*)gemm_tc<1,false,false>, cudaFuncAttributeMaxDynamicSharedMemorySize, GSMEM_TOTAL);
    cudaFuncSetAttribute((const void*)gemm_tc<0,true,false>,  cudaFuncAttributeMaxDynamicSharedMemorySize, GSMEM_TOTAL);
    cudaFuncSetAttribute((const void*)gemm_tc<3,false,false>, cudaFuncAttributeMaxDynamicSharedMemorySize, GSMEM_TOTAL);

    dim3 gPatch(B_, T1_);
    patch_embed_kernel<<<gPatch, 256>>>(x, cls, Wp, bp, p_out);

    const int Mt = B_ * T1_;   // 16640 rows, /256 = 65 m-tiles
    for (int l = 0; l < 2; l++) {
        ln2d_kernel<<<B_, 256>>>(p_out, ln_w + l * ND_, ln_b + l * ND_, p_h);
        gemm_tc<0, false, true><<<dim3(768 / 128, Mt / 256), 512, GSMEM_TOTAL>>>(
            p_h, qkv_w + l * D_ * 768, qkv_b + l * 768, nullptr, p_qkv,
            Mt, 768, D_, D_);
        attn_kernel<<<dim3(H_, B_), 96>>>(p_qkv, p_out);
        ln2d_kernel<<<B_, 256>>>(p_out, ln_w + l * ND_, ln_b + l * ND_, p_h);
        if (l == 0) {
            gemm_tc<1, false, true><<<dim3(MLPH_ / 128, Mt / 256), 512, GSMEM_TOTAL>>>(
                p_h, mlp1_w + l * D_ * MLPH_, mlp1_b + l * MLPH_, nullptr, p_m,
                Mt, MLPH_, D_, D_);
            gemm_tc<0, true, true><<<dim3(D_ / 128, Mt / 256), 512, GSMEM_TOTAL>>>(
                p_m, mlp2_w + l * MLPH_ * D_, mlp2_b + l * D_, p_out, p_out,
                Mt, D_, MLPH_, MLPH_);
        } else {
            // layer 2: W errors reach the output only through head1 — 1-term ok
            gemm_tc<1, false, false><<<dim3(MLPH_ / 128, Mt / 256), 512, GSMEM_TOTAL>>>(
                p_h, mlp1_w + l * D_ * MLPH_, mlp1_b + l * MLPH_, nullptr, p_m,
                Mt, MLPH_, D_, D_);
            gemm_tc<0, true, false><<<dim3(D_ / 128, Mt / 256), 512, GSMEM_TOTAL>>>(
                p_m, mlp2_w + l * MLPH_ * D_, mlp2_b + l * D_, p_out, p_out,
                Mt, D_, MLPH_, MLPH_);
        }
    }

    // head1 split-K (1-term fp16 W): partials then fused reduce+bias+silu
    gemm_tc<3, false, false><<<dim3(HEADH_ / 128, B_ / 256, SPLITK), 512, GSMEM_TOTAL>>>(
        p_out, h1w, h1b, nullptr, p_part, B_, HEADH_, ND_, KCHUNK);
    reduce_silu_kernel<<<(B_ * HEADH_) / 1024, 256>>>(p_part, h1b, p_hid);

    head2_kernel<<<B_, 256>>>(p_hid, h2w, h2b, out);
}

// round 16
// speedup vs baseline: 1.5668x; 1.1499x over previous
#include <cuda_runtime.h>
#include <cuda_fp16.h>
#include <math.h>
#include <stdint.h>

#define B_    256
#define C_    3
#define IMG_  32
#define D_    256
#define H_    8
#define HD_   32
#define T1_   65
#define MLPH_ 2048
#define HEADH_ 8192
#define NCLS_ 10
#define PDIM_ 48
#define ND_   (T1_*D_)   // 16640
#define SPLITK 4
#define KCHUNK (ND_/SPLITK)   // 4160

// ---------------- scratch ----------------------------------------------------
__device__ float g_out[B_*T1_*D_];
__device__ float g_h[B_*T1_*D_];
__device__ float g_qkv[B_*T1_*3*D_];
__device__ float g_m[B_*T1_*MLPH_];
__device__ float g_hid[B_*HEADH_];
__device__ float g_part[SPLITK*B_*HEADH_];

// ---------------- patch embed + cls + positional encoding --------------------
__global__ void patch_embed_kernel(const float* __restrict__ x,
                                   const float* __restrict__ cls,
                                   const float* __restrict__ Wp,
                                   const float* __restrict__ bp,
                                   float* __restrict__ out) {
    int b = blockIdx.x;
    int t = blockIdx.y;
    int d = threadIdx.x;
    int i = d >> 1;
    float div = expf(-(float)(2 * i) * (9.210340371976184f / 256.0f));
    float ang = (float)t * div;
    float pe = (d & 1) ? cosf(ang) : sinf(ang);

    if (t == 0) {
        out[(b * T1_) * D_ + d] = cls[d] + pe;
    } else {
        __shared__ float sp[PDIM_];
        int tt = t - 1;
        int ni = tt >> 3, nj = tt & 7;
        if (d < PDIM_) {
            int c  = d / 16;
            int pi = (d >> 2) & 3;
            int pj = d & 3;
            sp[d] = x[((b * C_ + c) * IMG_ + ni * 4 + pi) * IMG_ + nj * 4 + pj];
        }
        __syncthreads();
        float acc = bp[d];
        #pragma unroll
        for (int k = 0; k < PDIM_; k++) acc += sp[k] * Wp[k * D_ + d];
        out[((b * T1_) + t) * D_ + d] = acc + pe;
    }
}

// ---------------- LayerNorm over whole (T1,D) slab per sample ----------------
__global__ void ln2d_kernel(const float* __restrict__ X,
                            const float* __restrict__ w,
                            const float* __restrict__ bb,
                            float* __restrict__ Y) {
    int b = blockIdx.x;
    const float* xb = X + b * ND_;
    float s = 0.f, s2 = 0.f;
    for (int i = threadIdx.x; i < ND_; i += 256) {
        float v = xb[i];
        s += v; s2 += v * v;
    }
    __shared__ float rs[8], rs2[8], bc[2];
    #pragma unroll
    for (int o = 16; o > 0; o >>= 1) {
        s  += __shfl_down_sync(0xffffffffu, s,  o);
        s2 += __shfl_down_sync(0xffffffffu, s2, o);
    }
    int wid = threadIdx.x >> 5, lid = threadIdx.x & 31;
    if (lid == 0) { rs[wid] = s; rs2[wid] = s2; }
    __syncthreads();
    if (threadIdx.x == 0) {
        float ts = 0.f, ts2 = 0.f;
        #pragma unroll
        for (int k = 0; k < 8; k++) { ts += rs[k]; ts2 += rs2[k]; }
        float mu  = ts / (float)ND_;
        float var = ts2 / (float)ND_ - mu * mu;
        bc[0] = mu;
        bc[1] = rsqrtf(var + 1e-5f);
    }
    __syncthreads();
    float mu = bc[0], rsg = bc[1];
    float* yb = Y + b * ND_;
    for (int i = threadIdx.x; i < ND_; i += 256) {
        yb[i] = (xb[i] - mu) * rsg * w[i] + bb[i];
    }
}

// ---------------- fp16 tensor-core GEMM, BK=64, 3-stage pipeline --------------
// C(M,N) = act(A(M,K) @ W(K,N) + bias) (+R).
// A -> fp16 hi only; W -> fp16 hi (+ lo if WLO). fp32 accumulate.
// CTA tile 256x128, BK=64, 512 threads (16 warps), warp tile 64x32.
// ACT: 0 none, 1 relu, 2 silu, 3 raw partial (split-K, z-offset output)
#define PITCH 72                      // fp16 elements per smem row (64 + 8 pad)
#define SA_H 0                        // 256*72*2 = 36864
#define SB_H 36864                    // 128*72*2 = 18432
#define SB_L 55296
#define BUFSZ 73728
#define GSMEM_TOTAL (3*BUFSZ)         // 221184 (3-stage)

__device__ __forceinline__ void mma16816h(float* c, const uint32_t* a, const uint32_t* b) {
    asm volatile(
        "mma.sync.aligned.m16n8k16.row.col.f32.f16.f16.f32 "
        "{%0,%1,%2,%3}, {%4,%5,%6,%7}, {%8,%9}, {%0,%1,%2,%3};"
        : "+f"(c[0]), "+f"(c[1]), "+f"(c[2]), "+f"(c[3])
        : "r"(a[0]), "r"(a[1]), "r"(a[2]), "r"(a[3]), "r"(b[0]), "r"(b[1]));
}
__device__ __forceinline__ void split_pair_h(float x, float y, __half2& hi, __half2& lo) {
    hi = __floats2half2_rn(x, y);
    float2 hf = __half22float2(hi);
    lo = __floats2half2_rn(x - hf.x, y - hf.y);
}

template<int ACT, bool RES, bool WLO>
__global__ void __launch_bounds__(512, 1) gemm_tc(
    const float* __restrict__ A, const float* __restrict__ W,
    const float* __restrict__ bias, const float* __restrict__ R,
    float* __restrict__ Cc, int M, int N, int K, int kChunk)
{
    extern __shared__ char smem[];
    const int tid = threadIdx.x;
    const int wid = tid >> 5;
    const int lane = tid & 31;
    const int wm = wid >> 2, wn = wid & 3;       // 4x4 warps -> 64x32 tiles
    const int m0 = blockIdx.y * 256, n0 = blockIdx.x * 128;
    const int kbase = blockIdx.z * kChunk;
    float* Cz = Cc + (long)blockIdx.z * M * N;
    const int gid = lane >> 2, tig = lane & 3;

    const int bn = tid & 127;                    // W fill: n index
    const int bkh = (tid >> 7) * 16;             // W fill: k group of 16

    float c[4][4][4];
    #pragma unroll
    for (int i = 0; i < 4; i++)
        #pragma unroll
        for (int j = 0; j < 4; j++)
            #pragma unroll
            for (int r = 0; r < 4; r++) c[i][j][r] = 0.f;

    const int nk = kChunk / 64;
    uint32_t rah[16];                 // A hi: 8 float4 -> 16 half2
    uint32_t rwh[8], rwl[8];          // W hi/lo

    auto ldg_tile = [&](int t) {
        #pragma unroll
        for (int i = 0; i < 8; i++) {
            int lin = tid + i * 512;
            int row = lin >> 4, q = lin & 15;
            float4 v = *(const float4*)&A[(long)(m0 + row) * K + kbase + t * 64 + q * 4];
            __half2 h0 = __floats2half2_rn(v.x, v.y);
            __half2 h1 = __floats2half2_rn(v.z, v.w);
            rah[2 * i]     = *(uint32_t*)&h0;
            rah[2 * i + 1] = *(uint32_t*)&h1;
        }
        const float* Wb = W + (long)(kbase + t * 64 + bkh) * N + n0 + bn;
        #pragma unroll
        for (int p = 0; p < 8; p++) {
            float w0 = Wb[(long)(2 * p) * N];
            float w1 = Wb[(long)(2 * p + 1) * N];
            if (WLO) {
                __half2 h, l;
                split_pair_h(w0, w1, h, l);
                rwh[p] = *(uint32_t*)&h;
                rwl[p] = *(uint32_t*)&l;
            } else {
                __half2 h = __floats2half2_rn(w0, w1);
                rwh[p] = *(uint32_t*)&h;
            }
        }
    };
    auto sts_tile = [&](int buf) {
        char* base = smem + buf * BUFSZ;
        #pragma unroll
        for (int i = 0; i < 8; i++) {
            int lin = tid + i * 512;
            int row = lin >> 4, q = lin & 15;
            int e = row * PITCH + q * 4;
            *(uint2*)(base + SA_H + e * 2) = make_uint2(rah[2 * i], rah[2 * i + 1]);
        }
        #pragma unroll
        for (int p = 0; p < 8; p++) {
            int e = bn * PITCH + bkh + 2 * p;
            *(uint32_t*)(base + SB_H + e * 2) = rwh[p];
            if (WLO) *(uint32_t*)(base + SB_L + e * 2) = rwl[p];
        }
    };

    // 3-stage prologue: tile0 in smem, tile1 in regs
    ldg_tile(0);
    sts_tile(0);
    if (nk > 1) ldg_tile(1);
    __syncthreads();

    for (int t = 0; t < nk; t++) {
        const int buf = t % 3;
        if (t + 1 < nk) sts_tile((t + 1) % 3);
        if (t + 2 < nk) ldg_tile(t + 2);

        const char* ahp = smem + buf * BUFSZ + SA_H;
        const char* bhp = smem + buf * BUFSZ + SB_H;
        const char* blp = smem + buf * BUFSZ + SB_L;

        #pragma unroll
        for (int ks = 0; ks < 4; ks++) {
            const int acol = ks * 16 + tig * 2;
            uint32_t bh[4][2], bl[4][2];
            #pragma unroll
            for (int an = 0; an < 4; an++) {
                const int brow = wn * 32 + an * 8 + gid;
                const int e = (brow * PITCH + acol) * 2;
                bh[an][0] = *(const uint32_t*)(bhp + e);
                bh[an][1] = *(const uint32_t*)(bhp + e + 16);
                if (WLO) {
                    bl[an][0] = *(const uint32_t*)(blp + e);
                    bl[an][1] = *(const uint32_t*)(blp + e + 16);
                }
            }
            #pragma unroll
            for (int am = 0; am < 4; am++) {
                const int arow = wm * 64 + am * 16 + gid;
                const int e00 = (arow * PITCH + acol) * 2;
                const int e10 = ((arow + 8) * PITCH + acol) * 2;
                uint32_t ah[4];
                ah[0] = *(const uint32_t*)(ahp + e00);
                ah[1] = *(const uint32_t*)(ahp + e10);
                ah[2] = *(const uint32_t*)(ahp + e00 + 16);
                ah[3] = *(const uint32_t*)(ahp + e10 + 16);
                #pragma unroll
                for (int an = 0; an < 4; an++) {
                    mma16816h(c[am][an], ah, bh[an]);
                    if (WLO) mma16816h(c[am][an], ah, bl[an]);
                }
            }
        }
        __syncthreads();
    }

    // ---- epilogue ----
    #pragma unroll
    for (int am = 0; am < 4; am++) {
        #pragma unroll
        for (int an = 0; an < 4; an++) {
            const int col = n0 + wn * 32 + an * 8 + tig * 2;
            float bx = 0.f, by = 0.f;
            if (ACT != 3) { bx = bias[col]; by = bias[col + 1]; }
            #pragma unroll
            for (int hrow = 0; hrow < 2; hrow++) {
                const int m = m0 + wm * 64 + am * 16 + gid + hrow * 8;
                float vx = c[am][an][hrow * 2 + 0] + bx;
                float vy = c[am][an][hrow * 2 + 1] + by;
                if (ACT == 1) { vx = fmaxf(vx, 0.f); vy = fmaxf(vy, 0.f); }
                if (ACT == 2) {
                    vx = vx / (1.f + expf(-vx));
                    vy = vy / (1.f + expf(-vy));
                }
                if (RES) {
                    const float2 r2 = *(const float2*)&R[(long)m * N + col];
                    vx += r2.x; vy += r2.y;
                }
                *(float2*)&Cz[(long)m * N + col] = make_float2(vx, vy);
            }
        }
    }
}

// ---------------- split-K reduce + bias + silu --------------------------------
__global__ void reduce_silu_kernel(const float* __restrict__ part,
                                   const float* __restrict__ bias,
                                   float* __restrict__ out) {
    const long MN = (long)B_ * HEADH_;
    const long e = ((long)blockIdx.x * 256 + threadIdx.x) * 4;
    const int n = (int)(e % HEADH_);
    float4 a = *(const float4*)&part[e];
    #pragma unroll
    for (int z = 1; z < SPLITK; z++) {
        const float4 p = *(const float4*)&part[z * MN + e];
        a.x += p.x; a.y += p.y; a.z += p.z; a.w += p.w;
    }
    const float4 bi = *(const float4*)&bias[n];
    a.x += bi.x; a.y += bi.y; a.z += bi.z; a.w += bi.w;
    a.x = a.x / (1.f + expf(-a.x));
    a.y = a.y / (1.f + expf(-a.y));
    a.z = a.z / (1.f + expf(-a.z));
    a.w = a.w / (1.f + expf(-a.w));
    *(float4*)&out[e] = a;
}

// ---------------- fused attention per (b,h); out += attn ---------------------
__global__ __launch_bounds__(96)
void attn_kernel(const float* __restrict__ qkv, float* __restrict__ out) {
    const int h = blockIdx.x, b = blockIdx.y;
    __shared__ __align__(16) float Ks[T1_ * 32];
    __shared__ __align__(16) float Vs[T1_ * 32];
    __shared__ float S[T1_ * 67];
    const float* base = qkv + (long)b * T1_ * 768 + h * 96;

    for (int idx = threadIdx.x; idx < T1_ * 8; idx += 96) {
        int r = idx >> 3, c4 = (idx & 7) << 2;
        *(float4*)&Ks[r * 32 + c4] = *(const float4*)&base[r * 768 + 32 + c4];
        *(float4*)&Vs[r * 32 + c4] = *(const float4*)&base[r * 768 + 64 + c4];
    }
    __syncthreads();

    const int r = threadIdx.x;
    if (r < T1_) {
        float4 q4[8];
        #pragma unroll
        for (int j = 0; j < 8; j++)
            q4[j] = *(const float4*)&base[r * 768 + j * 4];

        float mx = -1e30f;
        for (int k = 0; k < T1_; k++) {
            float acc = 0.f;
            #pragma unroll
            for (int j = 0; j < 8; j++) {
                const float4 kv = *(const float4*)&Ks[k * 32 + j * 4];
                acc += q4[j].x * kv.x + q4[j].y * kv.y + q4[j].z * kv.z + q4[j].w * kv.w;
            }
            acc *= 0.17677669529663687f;
            S[r * 67 + k] = acc;
            mx = fmaxf(mx, acc);
        }
        float sum = 0.f;
        for (int k = 0; k < T1_; k++) {
            float e = expf(S[r * 67 + k] - mx);
            S[r * 67 + k] = e;
            sum += e;
        }
        const float inv = 1.f / sum;

        float4 acc4[8];
        #pragma unroll
        for (int j = 0; j < 8; j++) acc4[j] = make_float4(0.f, 0.f, 0.f, 0.f);
        for (int k = 0; k < T1_; k++) {
            const float s = S[r * 67 + k];
            #pragma unroll
            for (int j = 0; j < 8; j++) {
                const float4 vv = *(const float4*)&Vs[k * 32 + j * 4];
                acc4[j].x += s * vv.x; acc4[j].y += s * vv.y;
                acc4[j].z += s * vv.z; acc4[j].w += s * vv.w;
            }
        }
        float* op = out + ((long)b * T1_ + r) * D_ + h * HD_;
        #pragma unroll
        for (int j = 0; j < 8; j++) {
            float4 o = *(float4*)&op[j * 4];
            o.x += acc4[j].x * inv; o.y += acc4[j].y * inv;
            o.z += acc4[j].z * inv; o.w += acc4[j].w * inv;
            *(float4*)&op[j * 4] = o;
        }
    }
}

// ---------------- final classifier head --------------------------------------
__global__ void head2_kernel(const float* __restrict__ hid, const float* __restrict__ W2,
                             const float* __restrict__ b2, float* __restrict__ out) {
    int b = blockIdx.x;
    float acc[NCLS_] = {};
    for (int k = threadIdx.x; k < HEADH_; k += 256) {
        float hv = hid[(long)b * HEADH_ + k];
        #pragma unroll
        for (int c = 0; c < NCLS_; c++) acc[c] += hv * W2[k * NCLS_ + c];
    }
    __shared__ float red[256];
    for (int c = 0; c < NCLS_; c++) {
        red[threadIdx.x] = acc[c];
        __syncthreads();
        for (int o = 128; o > 0; o >>= 1) {
            if (threadIdx.x < o) red[threadIdx.x] += red[threadIdx.x + o];
            __syncthreads();
        }
        if (threadIdx.x == 0) out[b * NCLS_ + c] = red[0] + b2[c];
        __syncthreads();
    }
}

// -----------------------------------------------------------------------------
extern "C" void kernel_launch(void* const* d_in, const int* in_sizes, int n_in,
                              void* d_out, int out_size) {
    const float* x      = (const float*)d_in[0];
    const float* cls    = (const float*)d_in[1];
    const float* Wp     = (const float*)d_in[2];
    const float* bp     = (const float*)d_in[3];
    const float* qkv_w  = (const float*)d_in[4];
    const float* qkv_b  = (const float*)d_in[5];
    const float* ln_w   = (const float*)d_in[6];
    const float* ln_b   = (const float*)d_in[7];
    const float* mlp1_w = (const float*)d_in[8];
    const float* mlp1_b = (const float*)d_in[9];
    const float* mlp2_w = (const float*)d_in[10];
    const float* mlp2_b = (const float*)d_in[11];
    const float* h1w    = (const float*)d_in[12];
    const float* h1b    = (const float*)d_in[13];
    const float* h2w    = (const float*)d_in[14];
    const float* h2b    = (const float*)d_in[15];
    float* out = (float*)d_out;

    float *p_out, *p_h, *p_qkv, *p_m, *p_hid, *p_part;
    cudaGetSymbolAddress((void**)&p_out, g_out);
    cudaGetSymbolAddress((void**)&p_h,   g_h);
    cudaGetSymbolAddress((void**)&p_qkv, g_qkv);
    cudaGetSymbolAddress((void**)&p_m,   g_m);
    cudaGetSymbolAddress((void**)&p_hid, g_hid);
    cudaGetSymbolAddress((void**)&p_part, g_part);

    cudaFuncSetAttribute((const void*)gemm_tc<0,false,false>, cudaFuncAttributeMaxDynamicSharedMemorySize, GSMEM_TOTAL);
    cudaFuncSetAttribute((const void*)gemm_tc<1,false,false>, cudaFuncAttributeMaxDynamicSharedMemorySize, GSMEM_TOTAL);
    cudaFuncSetAttribute((const void*)gemm_tc<0,true,false>,  cudaFuncAttributeMaxDynamicSharedMemorySize, GSMEM_TOTAL);
    cudaFuncSetAttribute((const void*)gemm_tc<3,false,false>, cudaFuncAttributeMaxDynamicSharedMemorySize, GSMEM_TOTAL);

    dim3 gPatch(B_, T1_);
    patch_embed_kernel<<<gPatch, 256>>>(x, cls, Wp, bp, p_out);

    const int Mt = B_ * T1_;   // 16640 rows, /256 = 65 m-tiles
    for (int l = 0; l < 2; l++) {
        ln2d_kernel<<<B_, 256>>>(p_out, ln_w + l * ND_, ln_b + l * ND_, p_h);
        gemm_tc<0, false, false><<<dim3(768 / 128, Mt / 256), 512, GSMEM_TOTAL>>>(
            p_h, qkv_w + l * D_ * 768, qkv_b + l * 768, nullptr, p_qkv,
            Mt, 768, D_, D_);
        attn_kernel<<<dim3(H_, B_), 96>>>(p_qkv, p_out);
        ln2d_kernel<<<B_, 256>>>(p_out, ln_w + l * ND_, ln_b + l * ND_, p_h);
        gemm_tc<1, false, false><<<dim3(MLPH_ / 128, Mt / 256), 512, GSMEM_TOTAL>>>(
            p_h, mlp1_w + l * D_ * MLPH_, mlp1_b + l * MLPH_, nullptr, p_m,
            Mt, MLPH_, D_, D_);
        gemm_tc<0, true, false><<<dim3(D_ / 128, Mt / 256), 512, GSMEM_TOTAL>>>(
            p_m, mlp2_w + l * MLPH_ * D_, mlp2_b + l * D_, p_out, p_out,
            Mt, D_, MLPH_, MLPH_);
    }

    // head1 split-K (1-term fp16 W): partials then fused reduce+bias+silu
    gemm_tc<3, false, false><<<dim3(HEADH_ / 128, B_ / 256, SPLITK), 512, GSMEM_TOTAL>>>(
        p_out, h1w, h1b, nullptr, p_part, B_, HEADH_, ND_, KCHUNK);
    reduce_silu_kernel<<<(B_ * HEADH_) / 1024, 256>>>(p_part, h1b, p_hid);

    head2_kernel<<<B_, 256>>>(p_hid, h2w, h2b, out);
}

// round 17
// speedup vs baseline: 1.8355x; 1.1715x over previous
#include <cuda_runtime.h>
#include <cuda_fp16.h>
#include <math.h>
#include <stdint.h>

#define B_    256
#define C_    3
#define IMG_  32
#define D_    256
#define H_    8
#define HD_   32
#define T1_   65
#define MLPH_ 2048
#define HEADH_ 8192
#define NCLS_ 10
#define PDIM_ 48
#define ND_   (T1_*D_)   // 16640
#define SPLITK 4
#define KCHUNK (ND_/SPLITK)   // 4160

// ---------------- scratch ----------------------------------------------------
__device__ float  g_out[B_*T1_*D_];
__device__ float  g_qkv[B_*T1_*3*D_];
__device__ float  g_hid[B_*HEADH_];
__device__ float  g_part[SPLITK*B_*HEADH_];
__device__ __half g_hh[(long)ND_*B_];            // LN output, fp16
__device__ __half g_m16[(long)B_*T1_*MLPH_];     // mlp hidden, fp16
__device__ __half g_po16[(long)ND_*B_];          // final residual, fp16 (head1 A)

// ---------------- patch embed + cls + positional encoding --------------------
__global__ void patch_embed_kernel(const float* __restrict__ x,
                                   const float* __restrict__ cls,
                                   const float* __restrict__ Wp,
                                   const float* __restrict__ bp,
                                   float* __restrict__ out) {
    int b = blockIdx.x;
    int t = blockIdx.y;
    int d = threadIdx.x;
    int i = d >> 1;
    float div = expf(-(float)(2 * i) * (9.210340371976184f / 256.0f));
    float ang = (float)t * div;
    float pe = (d & 1) ? cosf(ang) : sinf(ang);

    if (t == 0) {
        out[(b * T1_) * D_ + d] = cls[d] + pe;
    } else {
        __shared__ float sp[PDIM_];
        int tt = t - 1;
        int ni = tt >> 3, nj = tt & 7;
        if (d < PDIM_) {
            int c  = d / 16;
            int pi = (d >> 2) & 3;
            int pj = d & 3;
            sp[d] = x[((b * C_ + c) * IMG_ + ni * 4 + pi) * IMG_ + nj * 4 + pj];
        }
        __syncthreads();
        float acc = bp[d];
        #pragma unroll
        for (int k = 0; k < PDIM_; k++) acc += sp[k] * Wp[k * D_ + d];
        out[((b * T1_) + t) * D_ + d] = acc + pe;
    }
}

// ---------------- LayerNorm over whole (T1,D) slab -> fp16 --------------------
__global__ void ln2d_kernel(const float* __restrict__ X,
                            const float* __restrict__ w,
                            const float* __restrict__ bb,
                            __half* __restrict__ Y) {
    int b = blockIdx.x;
    const float* xb = X + b * ND_;
    float s = 0.f, s2 = 0.f;
    for (int i = threadIdx.x; i < ND_; i += 256) {
        float v = xb[i];
        s += v; s2 += v * v;
    }
    __shared__ float rs[8], rs2[8], bc[2];
    #pragma unroll
    for (int o = 16; o > 0; o >>= 1) {
        s  += __shfl_down_sync(0xffffffffu, s,  o);
        s2 += __shfl_down_sync(0xffffffffu, s2, o);
    }
    int wid = threadIdx.x >> 5, lid = threadIdx.x & 31;
    if (lid == 0) { rs[wid] = s; rs2[wid] = s2; }
    __syncthreads();
    if (threadIdx.x == 0) {
        float ts = 0.f, ts2 = 0.f;
        #pragma unroll
        for (int k = 0; k < 8; k++) { ts += rs[k]; ts2 += rs2[k]; }
        float mu  = ts / (float)ND_;
        float var = ts2 / (float)ND_ - mu * mu;
        bc[0] = mu;
        bc[1] = rsqrtf(var + 1e-5f);
    }
    __syncthreads();
    float mu = bc[0], rsg = bc[1];
    __half* yb = Y + (long)b * ND_;
    for (int i = threadIdx.x; i < ND_; i += 256) {
        yb[i] = __float2half_rn((xb[i] - mu) * rsg * w[i] + bb[i]);
    }
}

// ---------------- fp32 residual -> fp16 copy ----------------------------------
__global__ void to_half_kernel(const float* __restrict__ X, __half* __restrict__ Y) {
    long i = ((long)blockIdx.x * 256 + threadIdx.x) * 4;
    float4 v = *(const float4*)&X[i];
    __half2 h0 = __floats2half2_rn(v.x, v.y);
    __half2 h1 = __floats2half2_rn(v.z, v.w);
    *(__half2*)&Y[i]     = h0;
    *(__half2*)&Y[i + 2] = h1;
}

// ---------------- fp16 tensor-core GEMM, BK=64, 3-stage pipeline --------------
// C(M,N) = act(A(M,K)@W(K,N)+bias) (+R).  A is fp16 in gmem; W fp32 -> fp16 hi.
// OUTH: write fp16 to Ch instead of fp32 to Cc.
// ACT: 0 none, 1 relu, 3 raw partial (split-K, z-offset output)
#define PITCH 72
#define SA_H 0                        // 256*72*2 = 36864
#define SB_H 36864
#define SB_L 55296
#define BUFSZ 73728
#define GSMEM_TOTAL (3*BUFSZ)

__device__ __forceinline__ void mma16816h(float* c, const uint32_t* a, const uint32_t* b) {
    asm volatile(
        "mma.sync.aligned.m16n8k16.row.col.f32.f16.f16.f32 "
        "{%0,%1,%2,%3}, {%4,%5,%6,%7}, {%8,%9}, {%0,%1,%2,%3};"
        : "+f"(c[0]), "+f"(c[1]), "+f"(c[2]), "+f"(c[3])
        : "r"(a[0]), "r"(a[1]), "r"(a[2]), "r"(a[3]), "r"(b[0]), "r"(b[1]));
}

template<int ACT, bool RES, bool OUTH>
__global__ void __launch_bounds__(512, 1) gemm_tc(
    const __half* __restrict__ A, const float* __restrict__ W,
    const float* __restrict__ bias, const float* __restrict__ R,
    float* __restrict__ Cc, __half* __restrict__ Ch,
    int M, int N, int K, int kChunk)
{
    extern __shared__ char smem[];
    const int tid = threadIdx.x;
    const int lane = tid & 31;
    const int wid = tid >> 5;
    const int wm = wid >> 2, wn = wid & 3;
    const int m0 = blockIdx.y * 256, n0 = blockIdx.x * 128;
    const int kbase = blockIdx.z * kChunk;
    const int gid = lane >> 2, tig = lane & 3;

    const int bn = tid & 127;
    const int bkh = (tid >> 7) * 16;

    float c[4][4][4];
    #pragma unroll
    for (int i = 0; i < 4; i++)
        #pragma unroll
        for (int j = 0; j < 4; j++)
            #pragma unroll
            for (int r = 0; r < 4; r++) c[i][j][r] = 0.f;

    const int nk = kChunk / 64;
    uint4 rah[4];                     // A: 256x64 fp16 = 2048 uint4, 4/thread
    uint32_t rwh[8];                  // W hi

    const int ar = tid >> 3, aq = tid & 7;   // 8 uint4 per 64-half row

    auto ldg_tile = [&](int t) {
        #pragma unroll
        for (int i = 0; i < 4; i++) {
            int lin = tid + i * 512;
            int row = lin >> 3, q = lin & 7;
            rah[i] = *(const uint4*)&A[(long)(m0 + row) * K + kbase + t * 64 + q * 8];
        }
        const float* Wb = W + (long)(kbase + t * 64 + bkh) * N + n0 + bn;
        #pragma unroll
        for (int p = 0; p < 8; p++) {
            float w0 = Wb[(long)(2 * p) * N];
            float w1 = Wb[(long)(2 * p + 1) * N];
            __half2 h = __floats2half2_rn(w0, w1);
            rwh[p] = *(uint32_t*)&h;
        }
    };
    auto sts_tile = [&](int buf) {
        char* base = smem + buf * BUFSZ;
        #pragma unroll
        for (int i = 0; i < 4; i++) {
            int lin = tid + i * 512;
            int row = lin >> 3, q = lin & 7;
            int e = row * PITCH + q * 8;
            *(uint4*)(base + SA_H + e * 2) = rah[i];
        }
        #pragma unroll
        for (int p = 0; p < 8; p++) {
            int e = bn * PITCH + bkh + 2 * p;
            *(uint32_t*)(base + SB_H + e * 2) = rwh[p];
        }
    };

    ldg_tile(0);
    sts_tile(0);
    if (nk > 1) ldg_tile(1);
    __syncthreads();

    for (int t = 0; t < nk; t++) {
        const int buf = t % 3;
        if (t + 1 < nk) sts_tile((t + 1) % 3);
        if (t + 2 < nk) ldg_tile(t + 2);

        const char* ahp = smem + buf * BUFSZ + SA_H;
        const char* bhp = smem + buf * BUFSZ + SB_H;

        #pragma unroll
        for (int ks = 0; ks < 4; ks++) {
            const int acol = ks * 16 + tig * 2;
            uint32_t bh[4][2];
            #pragma unroll
            for (int an = 0; an < 4; an++) {
                const int brow = wn * 32 + an * 8 + gid;
                const int e = (brow * PITCH + acol) * 2;
                bh[an][0] = *(const uint32_t*)(bhp + e);
                bh[an][1] = *(const uint32_t*)(bhp + e + 16);
            }
            #pragma unroll
            for (int am = 0; am < 4; am++) {
                const int arow = wm * 64 + am * 16 + gid;
                const int e00 = (arow * PITCH + acol) * 2;
                const int e10 = ((arow + 8) * PITCH + acol) * 2;
                uint32_t ah[4];
                ah[0] = *(const uint32_t*)(ahp + e00);
                ah[1] = *(const uint32_t*)(ahp + e10);
                ah[2] = *(const uint32_t*)(ahp + e00 + 16);
                ah[3] = *(const uint32_t*)(ahp + e10 + 16);
                #pragma unroll
                for (int an = 0; an < 4; an++)
                    mma16816h(c[am][an], ah, bh[an]);
            }
        }
        __syncthreads();
    }

    // ---- epilogue ----
    float* Cz = Cc + (long)blockIdx.z * M * N;
    #pragma unroll
    for (int am = 0; am < 4; am++) {
        #pragma unroll
        for (int an = 0; an < 4; an++) {
            const int col = n0 + wn * 32 + an * 8 + tig * 2;
            float bx = 0.f, by = 0.f;
            if (ACT != 3) { bx = bias[col]; by = bias[col + 1]; }
            #pragma unroll
            for (int hrow = 0; hrow < 2; hrow++) {
                const int m = m0 + wm * 64 + am * 16 + gid + hrow * 8;
                float vx = c[am][an][hrow * 2 + 0] + bx;
                float vy = c[am][an][hrow * 2 + 1] + by;
                if (ACT == 1) { vx = fmaxf(vx, 0.f); vy = fmaxf(vy, 0.f); }
                if (RES) {
                    const float2 r2 = *(const float2*)&R[(long)m * N + col];
                    vx += r2.x; vy += r2.y;
                }
                if (OUTH) {
                    *(__half2*)&Ch[(long)m * N + col] = __floats2half2_rn(vx, vy);
                } else {
                    *(float2*)&Cz[(long)m * N + col] = make_float2(vx, vy);
                }
            }
        }
    }
}

// ---------------- split-K reduce + bias + silu --------------------------------
__global__ void reduce_silu_kernel(const float* __restrict__ part,
                                   const float* __restrict__ bias,
                                   float* __restrict__ out) {
    const long MN = (long)B_ * HEADH_;
    const long e = ((long)blockIdx.x * 256 + threadIdx.x) * 4;
    const int n = (int)(e % HEADH_);
    float4 a = *(const float4*)&part[e];
    #pragma unroll
    for (int z = 1; z < SPLITK; z++) {
        const float4 p = *(const float4*)&part[z * MN + e];
        a.x += p.x; a.y += p.y; a.z += p.z; a.w += p.w;
    }
    const float4 bi = *(const float4*)&bias[n];
    a.x += bi.x; a.y += bi.y; a.z += bi.z; a.w += bi.w;
    a.x = a.x / (1.f + expf(-a.x));
    a.y = a.y / (1.f + expf(-a.y));
    a.z = a.z / (1.f + expf(-a.z));
    a.w = a.w / (1.f + expf(-a.w));
    *(float4*)&out[e] = a;
}

// ---------------- fused attention per (b,h); out += attn ---------------------
__global__ __launch_bounds__(96)
void attn_kernel(const float* __restrict__ qkv, float* __restrict__ out) {
    const int h = blockIdx.x, b = blockIdx.y;
    __shared__ __align__(16) float Ks[T1_ * 32];
    __shared__ __align__(16) float Vs[T1_ * 32];
    __shared__ float S[T1_ * 67];
    const float* base = qkv + (long)b * T1_ * 768 + h * 96;

    for (int idx = threadIdx.x; idx < T1_ * 8; idx += 96) {
        int r = idx >> 3, c4 = (idx & 7) << 2;
        *(float4*)&Ks[r * 32 + c4] = *(const float4*)&base[r * 768 + 32 + c4];
        *(float4*)&Vs[r * 32 + c4] = *(const float4*)&base[r * 768 + 64 + c4];
    }
    __syncthreads();

    const int r = threadIdx.x;
    if (r < T1_) {
        float4 q4[8];
        #pragma unroll
        for (int j = 0; j < 8; j++)
            q4[j] = *(const float4*)&base[r * 768 + j * 4];

        float mx = -1e30f;
        for (int k = 0; k < T1_; k++) {
            float acc = 0.f;
            #pragma unroll
            for (int j = 0; j < 8; j++) {
                const float4 kv = *(const float4*)&Ks[k * 32 + j * 4];
                acc += q4[j].x * kv.x + q4[j].y * kv.y + q4[j].z * kv.z + q4[j].w * kv.w;
            }
            acc *= 0.17677669529663687f;
            S[r * 67 + k] = acc;
            mx = fmaxf(mx, acc);
        }
        float sum = 0.f;
        for (int k = 0; k < T1_; k++) {
            float e = expf(S[r * 67 + k] - mx);
            S[r * 67 + k] = e;
            sum += e;
        }
        const float inv = 1.f / sum;

        float4 acc4[8];
        #pragma unroll
        for (int j = 0; j < 8; j++) acc4[j] = make_float4(0.f, 0.f, 0.f, 0.f);
        for (int k = 0; k < T1_; k++) {
            const float s = S[r * 67 + k];
            #pragma unroll
            for (int j = 0; j < 8; j++) {
                const float4 vv = *(const float4*)&Vs[k * 32 + j * 4];
                acc4[j].x += s * vv.x; acc4[j].y += s * vv.y;
                acc4[j].z += s * vv.z; acc4[j].w += s * vv.w;
            }
        }
        float* op = out + ((long)b * T1_ + r) * D_ + h * HD_;
        #pragma unroll
        for (int j = 0; j < 8; j++) {
            float4 o = *(float4*)&op[j * 4];
            o.x += acc4[j].x * inv; o.y += acc4[j].y * inv;
            o.z += acc4[j].z * inv; o.w += acc4[j].w * inv;
            *(float4*)&op[j * 4] = o;
        }
    }
}

// ---------------- final classifier head --------------------------------------
__global__ void head2_kernel(const float* __restrict__ hid, const float* __restrict__ W2,
                             const float* __restrict__ b2, float* __restrict__ out) {
    int b = blockIdx.x;
    float acc[NCLS_] = {};
    for (int k = threadIdx.x; k < HEADH_; k += 256) {
        float hv = hid[(long)b * HEADH_ + k];
        #pragma unroll
        for (int c = 0; c < NCLS_; c++) acc[c] += hv * W2[k * NCLS_ + c];
    }
    __shared__ float red[256];
    for (int c = 0; c < NCLS_; c++) {
        red[threadIdx.x] = acc[c];
        __syncthreads();
        for (int o = 128; o > 0; o >>= 1) {
            if (threadIdx.x < o) red[threadIdx.x] += red[threadIdx.x + o];
            __syncthreads();
        }
        if (threadIdx.x == 0) out[b * NCLS_ + c] = red[0] + b2[c];
        __syncthreads();
    }
}

// -----------------------------------------------------------------------------
extern "C" void kernel_launch(void* const* d_in, const int* in_sizes, int n_in,
                              void* d_out, int out_size) {
    const float* x      = (const float*)d_in[0];
    const float* cls    = (const float*)d_in[1];
    const float* Wp     = (const float*)d_in[2];
    const float* bp     = (const float*)d_in[3];
    const float* qkv_w  = (const float*)d_in[4];
    const float* qkv_b  = (const float*)d_in[5];
    const float* ln_w   = (const float*)d_in[6];
    const float* ln_b   = (const float*)d_in[7];
    const float* mlp1_w = (const float*)d_in[8];
    const float* mlp1_b = (const float*)d_in[9];
    const float* mlp2_w = (const float*)d_in[10];
    const float* mlp2_b = (const float*)d_in[11];
    const float* h1w    = (const float*)d_in[12];
    const float* h1b    = (const float*)d_in[13];
    const float* h2w    = (const float*)d_in[14];
    const float* h2b    = (const float*)d_in[15];
    float* out = (float*)d_out;

    float *p_out, *p_qkv, *p_hid, *p_part;
    __half *p_hh, *p_m16, *p_po16;
    cudaGetSymbolAddress((void**)&p_out, g_out);
    cudaGetSymbolAddress((void**)&p_qkv, g_qkv);
    cudaGetSymbolAddress((void**)&p_hid, g_hid);
    cudaGetSymbolAddress((void**)&p_part, g_part);
    cudaGetSymbolAddress((void**)&p_hh,  g_hh);
    cudaGetSymbolAddress((void**)&p_m16, g_m16);
    cudaGetSymbolAddress((void**)&p_po16, g_po16);

    cudaFuncSetAttribute((const void*)gemm_tc<0,false,false>, cudaFuncAttributeMaxDynamicSharedMemorySize, GSMEM_TOTAL);
    cudaFuncSetAttribute((const void*)gemm_tc<1,false,true>,  cudaFuncAttributeMaxDynamicSharedMemorySize, GSMEM_TOTAL);
    cudaFuncSetAttribute((const void*)gemm_tc<0,true,false>,  cudaFuncAttributeMaxDynamicSharedMemorySize, GSMEM_TOTAL);
    cudaFuncSetAttribute((const void*)gemm_tc<0,true,true>,   cudaFuncAttributeMaxDynamicSharedMemorySize, GSMEM_TOTAL);
    cudaFuncSetAttribute((const void*)gemm_tc<3,false,false>, cudaFuncAttributeMaxDynamicSharedMemorySize, GSMEM_TOTAL);

    dim3 gPatch(B_, T1_);
    patch_embed_kernel<<<gPatch, 256>>>(x, cls, Wp, bp, p_out);

    const int Mt = B_ * T1_;   // 16640
    for (int l = 0; l < 2; l++) {
        ln2d_kernel<<<B_, 256>>>(p_out, ln_w + l * ND_, ln_b + l * ND_, p_hh);
        gemm_tc<0, false, false><<<dim3(768 / 128, Mt / 256), 512, GSMEM_TOTAL>>>(
            p_hh, qkv_w + l * D_ * 768, qkv_b + l * 768, nullptr, p_qkv, nullptr,
            Mt, 768, D_, D_);
        attn_kernel<<<dim3(H_, B_), 96>>>(p_qkv, p_out);
        ln2d_kernel<<<B_, 256>>>(p_out, ln_w + l * ND_, ln_b + l * ND_, p_hh);
        gemm_tc<1, false, true><<<dim3(MLPH_ / 128, Mt / 256), 512, GSMEM_TOTAL>>>(
            p_hh, mlp1_w + l * D_ * MLPH_, mlp1_b + l * MLPH_, nullptr, nullptr, p_m16,
            Mt, MLPH_, D_, D_);
        if (l == 0) {
            gemm_tc<0, true, false><<<dim3(D_ / 128, Mt / 256), 512, GSMEM_TOTAL>>>(
                p_m16, mlp2_w + l * MLPH_ * D_, mlp2_b + l * D_, p_out, p_out, nullptr,
                Mt, D_, MLPH_, MLPH_);
        } else {
            // final residual: consumed only by head1 (fp16) -> write fp16 directly
            gemm_tc<0, true, true><<<dim3(D_ / 128, Mt / 256), 512, GSMEM_TOTAL>>>(
                p_m16, mlp2_w + l * MLPH_ * D_, mlp2_b + l * D_, p_out, nullptr, p_po16,
                Mt, D_, MLPH_, MLPH_);
        }
    }

    // head1 split-K (fp16 A + 1-term fp16 W): partials then fused reduce+silu
    gemm_tc<3, false, false><<<dim3(HEADH_ / 128, B_ / 256, SPLITK), 512, GSMEM_TOTAL>>>(
        p_po16, h1w, h1b, nullptr, p_part, nullptr, B_, HEADH_, ND_, KCHUNK);
    reduce_silu_kernel<<<(B_ * HEADH_) / 1024, 256>>>(p_part, h1b, p_hid);

    head2_kernel<<<B_, 256>>>(p_hid, h2w, h2b, out);
}